// round 1
// baseline (speedup 1.0000x reference)
#include <cuda_runtime.h>
#include <cuda_bf16.h>
#include <cstdint>

// Problem shape (fixed by the reference):
//   query: [B=16, Lq=2048, D=512] fp32
//   value: [B=16, Lv=2048, D=512] fp32
//   out  : context [B,Lq,D] fp32  followed by  attn [B,Lq,Lv] fp32
static constexpr int B_  = 16;
static constexpr int LQ  = 2048;
static constexpr int LV  = 2048;
static constexpr int DD  = 512;

// ---------------------------------------------------------------------------
// Tiled FP32 GEMM. C[M,N] = A[M,K] * B
//   B_NK = true : B is row-major [N,K]  (C = A * B^T)   -> S = Q * V^T
//   B_NK = false: B is row-major [K,N]  (C = A * B)     -> O = P * V
// Batched via blockIdx.z (dense strides M*K, N*K, M*N).
// 128x128 tile, BK=16, 256 threads, 8x8 per-thread micro-tile.
// ---------------------------------------------------------------------------
static constexpr int BM = 128, BN = 128, BK = 16, TM = 8, TN = 8;
static constexpr int PAD = 4;

template <bool B_NK>
__global__ __launch_bounds__(256, 2)
void sgemm_kernel(const float* __restrict__ A,
                  const float* __restrict__ Bm,
                  float* __restrict__ C,
                  int M, int N, int K)
{
    __shared__ float As[BK][BM + PAD];
    __shared__ float Bs[BK][BN + PAD];

    const int tid = threadIdx.x;
    const size_t bz = blockIdx.z;
    A  += bz * (size_t)M * K;
    Bm += bz * (size_t)N * K;
    C  += bz * (size_t)M * N;

    const int row0 = blockIdx.y * BM;
    const int col0 = blockIdx.x * BN;

    const int tr = tid / 16;          // 0..15 -> output row group
    const int tc = tid % 16;          // 0..15 -> output col group

    // A/B (K-contiguous) loader indices: 64 rows x 16 cols per pass
    const int alr = tid >> 2;         // 0..63
    const int alc = (tid & 3) * 4;    // 0,4,8,12
    // B (N-contiguous) loader indices: 8 k-rows x 128 cols per pass
    const int blr = tid >> 5;         // 0..7
    const int blc = (tid & 31) * 4;   // 0..124

    float acc[TM][TN];
#pragma unroll
    for (int i = 0; i < TM; ++i)
#pragma unroll
        for (int j = 0; j < TN; ++j) acc[i][j] = 0.f;

    float ra[TM], rb[TN];

    for (int k0 = 0; k0 < K; k0 += BK) {
        // --- load A tile (BM x BK), store transposed As[k][m]
#pragma unroll
        for (int r = 0; r < BM; r += 64) {
            float4 v = *(const float4*)&A[(size_t)(row0 + alr + r) * K + k0 + alc];
            As[alc + 0][alr + r] = v.x;
            As[alc + 1][alr + r] = v.y;
            As[alc + 2][alr + r] = v.z;
            As[alc + 3][alr + r] = v.w;
        }
        // --- load B tile (BK x BN into Bs[k][n])
        if (B_NK) {
#pragma unroll
            for (int r = 0; r < BN; r += 64) {
                float4 v = *(const float4*)&Bm[(size_t)(col0 + alr + r) * K + k0 + alc];
                Bs[alc + 0][alr + r] = v.x;
                Bs[alc + 1][alr + r] = v.y;
                Bs[alc + 2][alr + r] = v.z;
                Bs[alc + 3][alr + r] = v.w;
            }
        } else {
#pragma unroll
            for (int r = 0; r < BK; r += 8) {
                float4 v = *(const float4*)&Bm[(size_t)(k0 + blr + r) * N + col0 + blc];
                *(float4*)&Bs[blr + r][blc] = v;
            }
        }
        __syncthreads();

#pragma unroll
        for (int k = 0; k < BK; ++k) {
#pragma unroll
            for (int i = 0; i < TM; ++i) ra[i] = As[k][tr * TM + i];
#pragma unroll
            for (int j = 0; j < TN; ++j) rb[j] = Bs[k][tc * TN + j];
#pragma unroll
            for (int i = 0; i < TM; ++i)
#pragma unroll
                for (int j = 0; j < TN; ++j)
                    acc[i][j] = fmaf(ra[i], rb[j], acc[i][j]);
        }
        __syncthreads();
    }

    // --- write C tile
#pragma unroll
    for (int i = 0; i < TM; ++i) {
        float4* cp = (float4*)&C[(size_t)(row0 + tr * TM + i) * N + col0 + tc * TN];
        cp[0] = make_float4(acc[i][0], acc[i][1], acc[i][2], acc[i][3]);
        cp[1] = make_float4(acc[i][4], acc[i][5], acc[i][6], acc[i][7]);
    }
}

// ---------------------------------------------------------------------------
// In-place row softmax over Lv=2048 columns. One block (256 threads) per row,
// 8 elements per thread (two float4).
// ---------------------------------------------------------------------------
__global__ __launch_bounds__(256)
void softmax_kernel(float* __restrict__ attn)
{
    const size_t row = blockIdx.x;
    float4* p = (float4*)(attn + row * (size_t)LV);
    const int tid = threadIdx.x;

    float4 v0 = p[tid * 2 + 0];
    float4 v1 = p[tid * 2 + 1];

    float m = fmaxf(fmaxf(fmaxf(v0.x, v0.y), fmaxf(v0.z, v0.w)),
                    fmaxf(fmaxf(v1.x, v1.y), fmaxf(v1.z, v1.w)));
#pragma unroll
    for (int o = 16; o > 0; o >>= 1)
        m = fmaxf(m, __shfl_xor_sync(0xffffffffu, m, o));

    __shared__ float red[8];
    if ((tid & 31) == 0) red[tid >> 5] = m;
    __syncthreads();
    float mall = red[0];
#pragma unroll
    for (int w = 1; w < 8; ++w) mall = fmaxf(mall, red[w]);
    __syncthreads();

    v0.x = __expf(v0.x - mall); v0.y = __expf(v0.y - mall);
    v0.z = __expf(v0.z - mall); v0.w = __expf(v0.w - mall);
    v1.x = __expf(v1.x - mall); v1.y = __expf(v1.y - mall);
    v1.z = __expf(v1.z - mall); v1.w = __expf(v1.w - mall);

    float s = v0.x + v0.y + v0.z + v0.w + v1.x + v1.y + v1.z + v1.w;
#pragma unroll
    for (int o = 16; o > 0; o >>= 1)
        s += __shfl_xor_sync(0xffffffffu, s, o);
    if ((tid & 31) == 0) red[tid >> 5] = s;
    __syncthreads();
    float sall = red[0];
#pragma unroll
    for (int w = 1; w < 8; ++w) sall += red[w];

    const float inv = 1.0f / sall;
    v0.x *= inv; v0.y *= inv; v0.z *= inv; v0.w *= inv;
    v1.x *= inv; v1.y *= inv; v1.z *= inv; v1.w *= inv;

    p[tid * 2 + 0] = v0;
    p[tid * 2 + 1] = v1;
}

// ---------------------------------------------------------------------------
extern "C" void kernel_launch(void* const* d_in, const int* in_sizes, int n_in,
                              void* d_out, int out_size)
{
    const float* Q = (const float*)d_in[0];
    const float* V = (const float*)d_in[1];

    float* ctx  = (float*)d_out;                                   // [B,Lq,D]
    float* attn = (float*)d_out + (size_t)B_ * LQ * DD;            // [B,Lq,Lv]

    // 1) scores S = Q * V^T  -> written into attn region
    {
        dim3 grid(LV / BN, LQ / BM, B_);
        sgemm_kernel<true><<<grid, 256>>>(Q, V, attn, LQ, LV, DD);
    }
    // 2) softmax rows in place
    {
        softmax_kernel<<<B_ * LQ, 256>>>(attn);
    }
    // 3) context = attn * V
    {
        dim3 grid(DD / BN, LQ / BM, B_);
        sgemm_kernel<false><<<grid, 256>>>(attn, V, ctx, LQ, DD, LV);
    }
}

// round 3
// speedup vs baseline: 1.3305x; 1.3305x over previous
#include <cuda_runtime.h>
#include <cuda_bf16.h>
#include <cstdint>

// Shape fixed by reference:
//   query [B=16, Lq=2048, D=512] f32, value [B=16, Lv=2048, D=512] f32
//   out = context [B,Lq,D] f32  ||  attn [B,Lq,Lv] f32
static constexpr int B_ = 16, LQ = 2048, LV = 2048, DD = 512;

// Scratch: V transposed per batch -> VT[b][d][v]
__device__ float g_VT[(size_t)B_ * DD * LV];

// ---------------------------------------------------------------------------
// cp.async helpers (sm_80+, valid on generic sm_103 target)
// ---------------------------------------------------------------------------
__device__ __forceinline__ void cp16(uint32_t dst, const void* src) {
    asm volatile("cp.async.cg.shared.global [%0], [%1], 16;" :: "r"(dst), "l"(src));
}
#define CP_COMMIT() asm volatile("cp.async.commit_group;" ::: "memory")
template <int N>
__device__ __forceinline__ void cp_wait() {
    asm volatile("cp.async.wait_group %0;" :: "n"(N) : "memory");
}

// 3xTF32 split: hi = rna_tf32(x), lo = rna_tf32(x - hi)
__device__ __forceinline__ void tf32_split(float x, uint32_t& hi, uint32_t& lo) {
    uint32_t h;
    asm("cvt.rna.tf32.f32 %0, %1;" : "=r"(h) : "f"(x));
    float l = x - __uint_as_float(h);
    uint32_t lu;
    asm("cvt.rna.tf32.f32 %0, %1;" : "=r"(lu) : "f"(l));
    hi = h; lo = lu;
}

__device__ __forceinline__ void mma8(float* d, const uint32_t* a, const uint32_t* b) {
    asm volatile(
        "mma.sync.aligned.m16n8k8.row.col.f32.tf32.tf32.f32 "
        "{%0,%1,%2,%3}, {%4,%5,%6,%7}, {%8,%9}, {%0,%1,%2,%3};"
        : "+f"(d[0]), "+f"(d[1]), "+f"(d[2]), "+f"(d[3])
        : "r"(a[0]), "r"(a[1]), "r"(a[2]), "r"(a[3]), "r"(b[0]), "r"(b[1]));
}

// ---------------------------------------------------------------------------
// TF32 tensor-core GEMM with 3xTF32 hi/lo compensation:
//   C[M,N] = A[M,K] * B[N,K]^T   (both operands row-major, K contiguous)
// CTA tile 128x128, BK=32 floats, 256 threads (8 warps, 2x4 of 64x32 tiles),
// 2-stage cp.async pipeline. smem rows padded to 36 floats (conflict-free).
// ---------------------------------------------------------------------------
static constexpr int LDS_ROW = 36;                     // floats per smem row
static constexpr int TILE_F  = 128 * LDS_ROW;          // floats per tile
static constexpr int GEMM_SMEM = 2 * 2 * TILE_F * 4;   // 73728 bytes

__global__ __launch_bounds__(256, 1)
void mma_tf32_gemm(const float* __restrict__ A, const float* __restrict__ Bm,
                   float* __restrict__ C, int M, int N, int K)
{
    extern __shared__ float sm[];
    const int tid  = threadIdx.x;
    const int wid  = tid >> 5, lane = tid & 31;
    const int gid  = lane >> 2, tig = lane & 3;
    const int wm   = wid & 1;        // 0..1  (64-row slabs)
    const int wn   = wid >> 1;       // 0..3  (32-col slabs)

    const size_t bz = blockIdx.z;
    A  += bz * (size_t)M * K;
    Bm += bz * (size_t)N * K;
    C  += bz * (size_t)M * N;
    const int row0 = blockIdx.y * 128;
    const int col0 = blockIdx.x * 128;

    // loader indices: 32 rows x 8 float4 per pass, 4 passes per tile
    const int lr = tid >> 3;          // 0..31
    const int lc = (tid & 7) * 4;     // 0,4,...,28
    const uint32_t smem_base = (uint32_t)__cvta_generic_to_shared(sm);

    auto load_stage = [&](int s, int k0) {
        const uint32_t a_off = smem_base + (uint32_t)(s * 2 * TILE_F) * 4u;
        const uint32_t b_off = smem_base + (uint32_t)((s * 2 + 1) * TILE_F) * 4u;
#pragma unroll
        for (int r = 0; r < 128; r += 32) {
            cp16(a_off + (uint32_t)((lr + r) * LDS_ROW + lc) * 4u,
                 &A[(size_t)(row0 + lr + r) * K + k0 + lc]);
            cp16(b_off + (uint32_t)((lr + r) * LDS_ROW + lc) * 4u,
                 &Bm[(size_t)(col0 + lr + r) * K + k0 + lc]);
        }
    };

    float acc[4][4][4];
#pragma unroll
    for (int mt = 0; mt < 4; ++mt)
#pragma unroll
        for (int nt = 0; nt < 4; ++nt)
#pragma unroll
            for (int i = 0; i < 4; ++i) acc[mt][nt][i] = 0.f;

    const int nsl = K / 32;
    load_stage(0, 0);
    CP_COMMIT();

    for (int s = 0; s < nsl; ++s) {
        if (s + 1 < nsl) {
            load_stage((s + 1) & 1, (s + 1) * 32);
            CP_COMMIT();
            cp_wait<1>();
        } else {
            cp_wait<0>();
        }
        __syncthreads();

        const float* Asm = sm + (s & 1) * 2 * TILE_F;
        const float* Bsm = sm + ((s & 1) * 2 + 1) * TILE_F;

#pragma unroll
        for (int ks = 0; ks < 4; ++ks) {
            uint32_t ahi[4][4], alo[4][4];
#pragma unroll
            for (int mt = 0; mt < 4; ++mt) {
                const int rb = wm * 64 + mt * 16;
                const int kc = ks * 8 + tig;
                float x0 = Asm[(rb + gid)     * LDS_ROW + kc];
                float x1 = Asm[(rb + gid + 8) * LDS_ROW + kc];
                float x2 = Asm[(rb + gid)     * LDS_ROW + kc + 4];
                float x3 = Asm[(rb + gid + 8) * LDS_ROW + kc + 4];
                tf32_split(x0, ahi[mt][0], alo[mt][0]);
                tf32_split(x1, ahi[mt][1], alo[mt][1]);
                tf32_split(x2, ahi[mt][2], alo[mt][2]);
                tf32_split(x3, ahi[mt][3], alo[mt][3]);
            }
            uint32_t bhi[4][2], blo[4][2];
#pragma unroll
            for (int nt = 0; nt < 4; ++nt) {
                const int nb = wn * 32 + nt * 8;
                const int kc = ks * 8 + tig;
                float y0 = Bsm[(nb + gid) * LDS_ROW + kc];
                float y1 = Bsm[(nb + gid) * LDS_ROW + kc + 4];
                tf32_split(y0, bhi[nt][0], blo[nt][0]);
                tf32_split(y1, bhi[nt][1], blo[nt][1]);
            }
#pragma unroll
            for (int mt = 0; mt < 4; ++mt)
#pragma unroll
                for (int nt = 0; nt < 4; ++nt) {
                    mma8(acc[mt][nt], ahi[mt], bhi[nt]);   // hi*hi
                    mma8(acc[mt][nt], ahi[mt], blo[nt]);   // hi*lo
                    mma8(acc[mt][nt], alo[mt], bhi[nt]);   // lo*hi
                }
        }
        __syncthreads();
    }

    // epilogue: c0,c1 at (row, 2*tig), c2,c3 at (row+8, 2*tig)
#pragma unroll
    for (int mt = 0; mt < 4; ++mt) {
        const int rb = row0 + wm * 64 + mt * 16 + gid;
#pragma unroll
        for (int nt = 0; nt < 4; ++nt) {
            const int cb = col0 + wn * 32 + nt * 8 + 2 * tig;
            *(float2*)&C[(size_t)rb * N + cb] =
                make_float2(acc[mt][nt][0], acc[mt][nt][1]);
            *(float2*)&C[(size_t)(rb + 8) * N + cb] =
                make_float2(acc[mt][nt][2], acc[mt][nt][3]);
        }
    }
}

// ---------------------------------------------------------------------------
// V transpose: VT[b][d][v] = V[b][v][d]
// ---------------------------------------------------------------------------
__global__ __launch_bounds__(256)
void transpose_vt_kernel(const float* __restrict__ V, float* __restrict__ VT)
{
    __shared__ float t[32][33];
    const int b = blockIdx.z;
    const float* Vb = V + (size_t)b * LV * DD;
    float* VTb = VT + (size_t)b * DD * LV;
    const int v0 = blockIdx.x * 32, d0 = blockIdx.y * 32;
    const int tx = threadIdx.x, ty = threadIdx.y;  // 32 x 8
#pragma unroll
    for (int i = 0; i < 32; i += 8)
        t[ty + i][tx] = Vb[(size_t)(v0 + ty + i) * DD + d0 + tx];
    __syncthreads();
#pragma unroll
    for (int i = 0; i < 32; i += 8)
        VTb[(size_t)(d0 + ty + i) * LV + v0 + tx] = t[tx][ty + i];
}

// ---------------------------------------------------------------------------
// In-place row softmax over Lv=2048
// ---------------------------------------------------------------------------
__global__ __launch_bounds__(256)
void softmax_kernel(float* __restrict__ attn)
{
    const size_t row = blockIdx.x;
    float4* p = (float4*)(attn + row * (size_t)LV);
    const int tid = threadIdx.x;

    float4 v0 = p[tid * 2 + 0];
    float4 v1 = p[tid * 2 + 1];

    float m = fmaxf(fmaxf(fmaxf(v0.x, v0.y), fmaxf(v0.z, v0.w)),
                    fmaxf(fmaxf(v1.x, v1.y), fmaxf(v1.z, v1.w)));
#pragma unroll
    for (int o = 16; o > 0; o >>= 1)
        m = fmaxf(m, __shfl_xor_sync(0xffffffffu, m, o));

    __shared__ float red[8];
    if ((tid & 31) == 0) red[tid >> 5] = m;
    __syncthreads();
    float mall = red[0];
#pragma unroll
    for (int w = 1; w < 8; ++w) mall = fmaxf(mall, red[w]);
    __syncthreads();

    v0.x = __expf(v0.x - mall); v0.y = __expf(v0.y - mall);
    v0.z = __expf(v0.z - mall); v0.w = __expf(v0.w - mall);
    v1.x = __expf(v1.x - mall); v1.y = __expf(v1.y - mall);
    v1.z = __expf(v1.z - mall); v1.w = __expf(v1.w - mall);

    float s = v0.x + v0.y + v0.z + v0.w + v1.x + v1.y + v1.z + v1.w;
#pragma unroll
    for (int o = 16; o > 0; o >>= 1)
        s += __shfl_xor_sync(0xffffffffu, s, o);
    if ((tid & 31) == 0) red[tid >> 5] = s;
    __syncthreads();
    float sall = red[0];
#pragma unroll
    for (int w = 1; w < 8; ++w) sall += red[w];

    const float inv = 1.0f / sall;
    v0.x *= inv; v0.y *= inv; v0.z *= inv; v0.w *= inv;
    v1.x *= inv; v1.y *= inv; v1.z *= inv; v1.w *= inv;

    p[tid * 2 + 0] = v0;
    p[tid * 2 + 1] = v1;
}

// ---------------------------------------------------------------------------
extern "C" void kernel_launch(void* const* d_in, const int* in_sizes, int n_in,
                              void* d_out, int out_size)
{
    const float* Q = (const float*)d_in[0];
    const float* V = (const float*)d_in[1];

    float* ctx  = (float*)d_out;                          // [B,Lq,D]
    float* attn = (float*)d_out + (size_t)B_ * LQ * DD;   // [B,Lq,Lv]

    cudaFuncSetAttribute(mma_tf32_gemm,
                         cudaFuncAttributeMaxDynamicSharedMemorySize, GEMM_SMEM);

    float* VT = nullptr;
    cudaGetSymbolAddress((void**)&VT, g_VT);

    // 0) VT = transpose(V)
    {
        dim3 grid(LV / 32, DD / 32, B_);
        transpose_vt_kernel<<<grid, dim3(32, 8)>>>(V, VT);
    }
    // 1) S = Q * V^T  (3xTF32 mma.sync) -> attn region
    {
        dim3 grid(LV / 128, LQ / 128, B_);
        mma_tf32_gemm<<<grid, 256, GEMM_SMEM>>>(Q, V, attn, LQ, LV, DD);
    }
    // 2) softmax rows in place
    softmax_kernel<<<B_ * LQ, 256>>>(attn);
    // 3) context = P * VT^T  (3xTF32 mma.sync)
    {
        dim3 grid(DD / 128, LQ / 128, B_);
        mma_tf32_gemm<<<grid, 256, GEMM_SMEM>>>(attn, VT, ctx, LQ, DD, LV);
    }
}

// round 4
// speedup vs baseline: 1.5513x; 1.1659x over previous
#include <cuda_runtime.h>
#include <cuda_bf16.h>
#include <cstdint>

// Shape fixed by reference:
//   query [B=16, Lq=2048, D=512] f32, value [B=16, Lv=2048, D=512] f32
//   out = context [B,Lq,D] f32  ||  attn [B,Lq,Lv] f32
static constexpr int B_ = 16, LQ = 2048, LV = 2048, DD = 512;

// Scratch: V transposed per batch -> VT[b][d][v]
__device__ float g_VT[(size_t)B_ * DD * LV];

// ---------------------------------------------------------------------------
// cp.async helpers
// ---------------------------------------------------------------------------
__device__ __forceinline__ void cp16(uint32_t dst, const void* src) {
    asm volatile("cp.async.cg.shared.global [%0], [%1], 16;" :: "r"(dst), "l"(src));
}
#define CP_COMMIT() asm volatile("cp.async.commit_group;" ::: "memory")
template <int N>
__device__ __forceinline__ void cp_wait() {
    asm volatile("cp.async.wait_group %0;" :: "n"(N) : "memory");
}

// tf32 hi part; lo = x - hi consumed raw (HW truncates mma operands to tf32)
__device__ __forceinline__ uint32_t tf32_hi(float x) {
    uint32_t h;
    asm("cvt.rna.tf32.f32 %0, %1;" : "=r"(h) : "f"(x));
    return h;
}

__device__ __forceinline__ void mma8(float* d, const uint32_t* a, const uint32_t* b) {
    asm volatile(
        "mma.sync.aligned.m16n8k8.row.col.f32.tf32.tf32.f32 "
        "{%0,%1,%2,%3}, {%4,%5,%6,%7}, {%8,%9}, {%0,%1,%2,%3};"
        : "+f"(d[0]), "+f"(d[1]), "+f"(d[2]), "+f"(d[3])
        : "r"(a[0]), "r"(a[1]), "r"(a[2]), "r"(a[3]), "r"(b[0]), "r"(b[1]));
}

// ---------------------------------------------------------------------------
// TF32 tensor-core GEMM with 3xTF32 hi/lo compensation:
//   C[M,N] = A[M,K] * B[N,K]^T   (both operands row-major, K contiguous)
// CTA tile 128x128, BK=32 floats, 256 threads (8 warps, 2x4 of 64x32 tiles),
// 2-stage cp.async pipeline, 2 CTAs/SM.
// ---------------------------------------------------------------------------
static constexpr int LDS_ROW = 36;                     // floats per smem row
static constexpr int TILE_F  = 128 * LDS_ROW;          // floats per tile
static constexpr int GEMM_SMEM = 2 * 2 * TILE_F * 4;   // 73728 bytes

__global__ __launch_bounds__(256, 2)
void mma_tf32_gemm(const float* __restrict__ A, const float* __restrict__ Bm,
                   float* __restrict__ C, int M, int N, int K)
{
    extern __shared__ float sm[];
    const int tid  = threadIdx.x;
    const int wid  = tid >> 5, lane = tid & 31;
    const int gid  = lane >> 2, tig = lane & 3;
    const int wm   = wid & 1;        // 0..1  (64-row slabs)
    const int wn   = wid >> 1;       // 0..3  (32-col slabs)

    const size_t bz = blockIdx.z;
    A  += bz * (size_t)M * K;
    Bm += bz * (size_t)N * K;
    C  += bz * (size_t)M * N;
    const int row0 = blockIdx.y * 128;
    const int col0 = blockIdx.x * 128;

    const int lr = tid >> 3;          // 0..31
    const int lc = (tid & 7) * 4;     // 0,4,...,28
    const uint32_t smem_base = (uint32_t)__cvta_generic_to_shared(sm);

    auto load_stage = [&](int s, int k0) {
        const uint32_t a_off = smem_base + (uint32_t)(s * 2 * TILE_F) * 4u;
        const uint32_t b_off = smem_base + (uint32_t)((s * 2 + 1) * TILE_F) * 4u;
#pragma unroll
        for (int r = 0; r < 128; r += 32) {
            cp16(a_off + (uint32_t)((lr + r) * LDS_ROW + lc) * 4u,
                 &A[(size_t)(row0 + lr + r) * K + k0 + lc]);
            cp16(b_off + (uint32_t)((lr + r) * LDS_ROW + lc) * 4u,
                 &Bm[(size_t)(col0 + lr + r) * K + k0 + lc]);
        }
    };

    float acc[4][4][4];
#pragma unroll
    for (int mt = 0; mt < 4; ++mt)
#pragma unroll
        for (int nt = 0; nt < 4; ++nt)
#pragma unroll
            for (int i = 0; i < 4; ++i) acc[mt][nt][i] = 0.f;

    const int nsl = K / 32;
    load_stage(0, 0);
    CP_COMMIT();

    for (int s = 0; s < nsl; ++s) {
        if (s + 1 < nsl) {
            load_stage((s + 1) & 1, (s + 1) * 32);
            CP_COMMIT();
            cp_wait<1>();
        } else {
            cp_wait<0>();
        }
        __syncthreads();

        const float* Asm = sm + (s & 1) * 2 * TILE_F;
        const float* Bsm = sm + ((s & 1) * 2 + 1) * TILE_F;

#pragma unroll
        for (int ks = 0; ks < 4; ++ks) {
            const int kc = ks * 8 + tig;

            // --- B fragments for this k-step: split once ---
            uint32_t bhi[4][2], blo[4][2];
#pragma unroll
            for (int nt = 0; nt < 4; ++nt) {
                const float* bp = Bsm + (wn * 32 + nt * 8 + gid) * LDS_ROW + kc;
                float y0 = bp[0], y1 = bp[4];
                bhi[nt][0] = tf32_hi(y0);
                blo[nt][0] = __float_as_uint(y0 - __uint_as_float(bhi[nt][0]));
                bhi[nt][1] = tf32_hi(y1);
                blo[nt][1] = __float_as_uint(y1 - __uint_as_float(bhi[nt][1]));
            }

            // --- A fragments per mt, then 12 MMAs ---
#pragma unroll
            for (int mt = 0; mt < 4; ++mt) {
                const float* ap = Asm + (wm * 64 + mt * 16 + gid) * LDS_ROW + kc;
                float x0 = ap[0];
                float x1 = ap[8 * LDS_ROW];
                float x2 = ap[4];
                float x3 = ap[8 * LDS_ROW + 4];
                uint32_t ahi[4], alo[4];
                ahi[0] = tf32_hi(x0); alo[0] = __float_as_uint(x0 - __uint_as_float(ahi[0]));
                ahi[1] = tf32_hi(x1); alo[1] = __float_as_uint(x1 - __uint_as_float(ahi[1]));
                ahi[2] = tf32_hi(x2); alo[2] = __float_as_uint(x2 - __uint_as_float(ahi[2]));
                ahi[3] = tf32_hi(x3); alo[3] = __float_as_uint(x3 - __uint_as_float(ahi[3]));
#pragma unroll
                for (int nt = 0; nt < 4; ++nt) {
                    mma8(acc[mt][nt], ahi, bhi[nt]);   // hi*hi
                    mma8(acc[mt][nt], ahi, blo[nt]);   // hi*lo
                    mma8(acc[mt][nt], alo, bhi[nt]);   // lo*hi
                }
            }
        }
        __syncthreads();
    }

    // epilogue: c0,c1 at (row, 2*tig), c2,c3 at (row+8, 2*tig)
#pragma unroll
    for (int mt = 0; mt < 4; ++mt) {
        const int rb = row0 + wm * 64 + mt * 16 + gid;
#pragma unroll
        for (int nt = 0; nt < 4; ++nt) {
            const int cb = col0 + wn * 32 + nt * 8 + 2 * tig;
            *(float2*)&C[(size_t)rb * N + cb] =
                make_float2(acc[mt][nt][0], acc[mt][nt][1]);
            *(float2*)&C[(size_t)(rb + 8) * N + cb] =
                make_float2(acc[mt][nt][2], acc[mt][nt][3]);
        }
    }
}

// ---------------------------------------------------------------------------
// V transpose: VT[b][d][v] = V[b][v][d]
// ---------------------------------------------------------------------------
__global__ __launch_bounds__(256)
void transpose_vt_kernel(const float* __restrict__ V, float* __restrict__ VT)
{
    __shared__ float t[32][33];
    const int b = blockIdx.z;
    const float* Vb = V + (size_t)b * LV * DD;
    float* VTb = VT + (size_t)b * DD * LV;
    const int v0 = blockIdx.x * 32, d0 = blockIdx.y * 32;
    const int tx = threadIdx.x, ty = threadIdx.y;  // 32 x 8
#pragma unroll
    for (int i = 0; i < 32; i += 8)
        t[ty + i][tx] = Vb[(size_t)(v0 + ty + i) * DD + d0 + tx];
    __syncthreads();
#pragma unroll
    for (int i = 0; i < 32; i += 8)
        VTb[(size_t)(d0 + ty + i) * LV + v0 + tx] = t[tx][ty + i];
}

// ---------------------------------------------------------------------------
// In-place row softmax over Lv=2048
// ---------------------------------------------------------------------------
__global__ __launch_bounds__(256)
void softmax_kernel(float* __restrict__ attn)
{
    const size_t row = blockIdx.x;
    float4* p = (float4*)(attn + row * (size_t)LV);
    const int tid = threadIdx.x;

    float4 v0 = p[tid * 2 + 0];
    float4 v1 = p[tid * 2 + 1];

    float m = fmaxf(fmaxf(fmaxf(v0.x, v0.y), fmaxf(v0.z, v0.w)),
                    fmaxf(fmaxf(v1.x, v1.y), fmaxf(v1.z, v1.w)));
#pragma unroll
    for (int o = 16; o > 0; o >>= 1)
        m = fmaxf(m, __shfl_xor_sync(0xffffffffu, m, o));

    __shared__ float red[8];
    if ((tid & 31) == 0) red[tid >> 5] = m;
    __syncthreads();
    float mall = red[0];
#pragma unroll
    for (int w = 1; w < 8; ++w) mall = fmaxf(mall, red[w]);
    __syncthreads();

    v0.x = __expf(v0.x - mall); v0.y = __expf(v0.y - mall);
    v0.z = __expf(v0.z - mall); v0.w = __expf(v0.w - mall);
    v1.x = __expf(v1.x - mall); v1.y = __expf(v1.y - mall);
    v1.z = __expf(v1.z - mall); v1.w = __expf(v1.w - mall);

    float s = v0.x + v0.y + v0.z + v0.w + v1.x + v1.y + v1.z + v1.w;
#pragma unroll
    for (int o = 16; o > 0; o >>= 1)
        s += __shfl_xor_sync(0xffffffffu, s, o);
    if ((tid & 31) == 0) red[tid >> 5] = s;
    __syncthreads();
    float sall = red[0];
#pragma unroll
    for (int w = 1; w < 8; ++w) sall += red[w];

    const float inv = 1.0f / sall;
    v0.x *= inv; v0.y *= inv; v0.z *= inv; v0.w *= inv;
    v1.x *= inv; v1.y *= inv; v1.z *= inv; v1.w *= inv;

    p[tid * 2 + 0] = v0;
    p[tid * 2 + 1] = v1;
}

// ---------------------------------------------------------------------------
extern "C" void kernel_launch(void* const* d_in, const int* in_sizes, int n_in,
                              void* d_out, int out_size)
{
    const float* Q = (const float*)d_in[0];
    const float* V = (const float*)d_in[1];

    float* ctx  = (float*)d_out;                          // [B,Lq,D]
    float* attn = (float*)d_out + (size_t)B_ * LQ * DD;   // [B,Lq,Lv]

    cudaFuncSetAttribute(mma_tf32_gemm,
                         cudaFuncAttributeMaxDynamicSharedMemorySize, GEMM_SMEM);

    float* VT = nullptr;
    cudaGetSymbolAddress((void**)&VT, g_VT);

    // 0) VT = transpose(V)
    {
        dim3 grid(LV / 32, DD / 32, B_);
        transpose_vt_kernel<<<grid, dim3(32, 8)>>>(V, VT);
    }
    // 1) S = Q * V^T  (3xTF32 mma.sync) -> attn region
    {
        dim3 grid(LV / 128, LQ / 128, B_);
        mma_tf32_gemm<<<grid, 256, GEMM_SMEM>>>(Q, V, attn, LQ, LV, DD);
    }
    // 2) softmax rows in place
    softmax_kernel<<<B_ * LQ, 256>>>(attn);
    // 3) context = P * VT^T  (3xTF32 mma.sync)
    {
        dim3 grid(DD / 128, LQ / 128, B_);
        mma_tf32_gemm<<<grid, 256, GEMM_SMEM>>>(attn, VT, ctx, LQ, DD, LV);
    }
}

// round 5
// speedup vs baseline: 1.6929x; 1.0913x over previous
#include <cuda_runtime.h>
#include <cuda_bf16.h>
#include <cstdint>

// Shape fixed by reference:
//   query [B=16, Lq=2048, D=512] f32, value [B=16, Lv=2048, D=512] f32
//   out = context [B,Lq,D] f32  ||  attn [B,Lq,Lv] f32
static constexpr int B_ = 16, LQ = 2048, LV = 2048, DD = 512;

// Scratch: V transposed per batch -> VT[b][d][v]
__device__ float g_VT[(size_t)B_ * DD * LV];

// ---------------------------------------------------------------------------
// cp.async helpers
// ---------------------------------------------------------------------------
__device__ __forceinline__ void cp16(uint32_t dst, const void* src) {
    asm volatile("cp.async.cg.shared.global [%0], [%1], 16;" :: "r"(dst), "l"(src));
}
#define CP_COMMIT() asm volatile("cp.async.commit_group;" ::: "memory")
template <int N>
__device__ __forceinline__ void cp_wait() {
    asm volatile("cp.async.wait_group %0;" :: "n"(N) : "memory");
}

// tf32 hi part; lo = x - hi consumed raw (HW truncates mma operands to tf32)
__device__ __forceinline__ uint32_t tf32_hi(float x) {
    uint32_t h;
    asm("cvt.rna.tf32.f32 %0, %1;" : "=r"(h) : "f"(x));
    return h;
}

__device__ __forceinline__ void mma8(float* d, const uint32_t* a, const uint32_t* b) {
    asm volatile(
        "mma.sync.aligned.m16n8k8.row.col.f32.tf32.tf32.f32 "
        "{%0,%1,%2,%3}, {%4,%5,%6,%7}, {%8,%9}, {%0,%1,%2,%3};"
        : "+f"(d[0]), "+f"(d[1]), "+f"(d[2]), "+f"(d[3])
        : "r"(a[0]), "r"(a[1]), "r"(a[2]), "r"(a[3]), "r"(b[0]), "r"(b[1]));
}

// ---------------------------------------------------------------------------
// TF32 tensor-core GEMM, C[M,N] = A[M,K] * B[N,K]^T (both row-major, K contig)
// PASSES = 3: hi*hi + hi*lo + lo*hi  (full 3xTF32 compensation)
// PASSES = 2: hi*hi + hi*lo          (A-lo term dropped; A in [0,1] softmax)
// CTA tile 128x128, BK=32, 256 threads (8 warps, 2x4 of 64x32 tiles),
// 3-stage cp.async pipeline with ONE __syncthreads per stage, 2 CTAs/SM.
// ---------------------------------------------------------------------------
static constexpr int LDS_ROW = 36;                       // floats per smem row
static constexpr int TILE_F  = 128 * LDS_ROW;            // floats per tile
static constexpr int STAGES  = 3;
static constexpr int GEMM_SMEM = STAGES * 2 * TILE_F * 4;  // 110592 bytes

template <int PASSES>
__global__ __launch_bounds__(256, 2)
void mma_tf32_gemm(const float* __restrict__ A, const float* __restrict__ Bm,
                   float* __restrict__ C, int M, int N, int K)
{
    extern __shared__ float sm[];
    const int tid  = threadIdx.x;
    const int wid  = tid >> 5, lane = tid & 31;
    const int gid  = lane >> 2, tig = lane & 3;
    const int wm   = wid & 1;        // 0..1  (64-row slabs)
    const int wn   = wid >> 1;       // 0..3  (32-col slabs)

    const size_t bz = blockIdx.z;
    A  += bz * (size_t)M * K;
    Bm += bz * (size_t)N * K;
    C  += bz * (size_t)M * N;
    const int row0 = blockIdx.y * 128;
    const int col0 = blockIdx.x * 128;

    const int lr = tid >> 3;          // 0..31
    const int lc = (tid & 7) * 4;     // 0,4,...,28
    const uint32_t smem_base = (uint32_t)__cvta_generic_to_shared(sm);

    auto load_stage = [&](int st, int k0) {
        const uint32_t a_off = smem_base + (uint32_t)(st * 2 * TILE_F) * 4u;
        const uint32_t b_off = smem_base + (uint32_t)((st * 2 + 1) * TILE_F) * 4u;
#pragma unroll
        for (int r = 0; r < 128; r += 32) {
            cp16(a_off + (uint32_t)((lr + r) * LDS_ROW + lc) * 4u,
                 &A[(size_t)(row0 + lr + r) * K + k0 + lc]);
            cp16(b_off + (uint32_t)((lr + r) * LDS_ROW + lc) * 4u,
                 &Bm[(size_t)(col0 + lr + r) * K + k0 + lc]);
        }
    };

    float acc[4][4][4];
#pragma unroll
    for (int mt = 0; mt < 4; ++mt)
#pragma unroll
        for (int nt = 0; nt < 4; ++nt)
#pragma unroll
            for (int i = 0; i < 4; ++i) acc[mt][nt][i] = 0.f;

    const int nsl = K / 32;
    load_stage(0, 0);  CP_COMMIT();
    load_stage(1, 32); CP_COMMIT();

    for (int s = 0; s < nsl; ++s) {
        cp_wait<1>();          // stage s resident (stage s+1 may be in flight)
        __syncthreads();       // also fences reuse of buffer (s+2)%3

        if (s + 2 < nsl) {     // issue loads 2 stages ahead
            load_stage((s + 2) % STAGES, (s + 2) * 32);
            CP_COMMIT();
        } else {
            CP_COMMIT();       // keep group count in step for cp_wait<1>
        }

        const float* Asm = sm + (s % STAGES) * 2 * TILE_F;
        const float* Bsm = sm + ((s % STAGES) * 2 + 1) * TILE_F;

#pragma unroll
        for (int ks = 0; ks < 4; ++ks) {
            const int kc = ks * 8 + tig;

            uint32_t bhi[4][2], blo[4][2];
#pragma unroll
            for (int nt = 0; nt < 4; ++nt) {
                const float* bp = Bsm + (wn * 32 + nt * 8 + gid) * LDS_ROW + kc;
                float y0 = bp[0], y1 = bp[4];
                bhi[nt][0] = tf32_hi(y0);
                blo[nt][0] = __float_as_uint(y0 - __uint_as_float(bhi[nt][0]));
                bhi[nt][1] = tf32_hi(y1);
                blo[nt][1] = __float_as_uint(y1 - __uint_as_float(bhi[nt][1]));
            }

#pragma unroll
            for (int mt = 0; mt < 4; ++mt) {
                const float* ap = Asm + (wm * 64 + mt * 16 + gid) * LDS_ROW + kc;
                float x0 = ap[0];
                float x1 = ap[8 * LDS_ROW];
                float x2 = ap[4];
                float x3 = ap[8 * LDS_ROW + 4];
                uint32_t ahi[4], alo[4];
                ahi[0] = tf32_hi(x0);
                ahi[1] = tf32_hi(x1);
                ahi[2] = tf32_hi(x2);
                ahi[3] = tf32_hi(x3);
                if (PASSES == 3) {
                    alo[0] = __float_as_uint(x0 - __uint_as_float(ahi[0]));
                    alo[1] = __float_as_uint(x1 - __uint_as_float(ahi[1]));
                    alo[2] = __float_as_uint(x2 - __uint_as_float(ahi[2]));
                    alo[3] = __float_as_uint(x3 - __uint_as_float(ahi[3]));
                }
#pragma unroll
                for (int nt = 0; nt < 4; ++nt) {
                    mma8(acc[mt][nt], ahi, bhi[nt]);        // hi*hi
                    mma8(acc[mt][nt], ahi, blo[nt]);        // hi*lo
                    if (PASSES == 3)
                        mma8(acc[mt][nt], alo, bhi[nt]);    // lo*hi
                }
            }
        }
    }

    // epilogue: c0,c1 at (row, 2*tig), c2,c3 at (row+8, 2*tig)
    __syncthreads();
#pragma unroll
    for (int mt = 0; mt < 4; ++mt) {
        const int rb = row0 + wm * 64 + mt * 16 + gid;
#pragma unroll
        for (int nt = 0; nt < 4; ++nt) {
            const int cb = col0 + wn * 32 + nt * 8 + 2 * tig;
            *(float2*)&C[(size_t)rb * N + cb] =
                make_float2(acc[mt][nt][0], acc[mt][nt][1]);
            *(float2*)&C[(size_t)(rb + 8) * N + cb] =
                make_float2(acc[mt][nt][2], acc[mt][nt][3]);
        }
    }
}

// ---------------------------------------------------------------------------
// V transpose: VT[b][d][v] = V[b][v][d]
// ---------------------------------------------------------------------------
__global__ __launch_bounds__(256)
void transpose_vt_kernel(const float* __restrict__ V, float* __restrict__ VT)
{
    __shared__ float t[32][33];
    const int b = blockIdx.z;
    const float* Vb = V + (size_t)b * LV * DD;
    float* VTb = VT + (size_t)b * DD * LV;
    const int v0 = blockIdx.x * 32, d0 = blockIdx.y * 32;
    const int tx = threadIdx.x, ty = threadIdx.y;  // 32 x 8
#pragma unroll
    for (int i = 0; i < 32; i += 8)
        t[ty + i][tx] = Vb[(size_t)(v0 + ty + i) * DD + d0 + tx];
    __syncthreads();
#pragma unroll
    for (int i = 0; i < 32; i += 8)
        VTb[(size_t)(d0 + ty + i) * LV + v0 + tx] = t[tx][ty + i];
}

// ---------------------------------------------------------------------------
// In-place row softmax over Lv=2048
// ---------------------------------------------------------------------------
__global__ __launch_bounds__(256)
void softmax_kernel(float* __restrict__ attn)
{
    const size_t row = blockIdx.x;
    float4* p = (float4*)(attn + row * (size_t)LV);
    const int tid = threadIdx.x;

    float4 v0 = p[tid * 2 + 0];
    float4 v1 = p[tid * 2 + 1];

    float m = fmaxf(fmaxf(fmaxf(v0.x, v0.y), fmaxf(v0.z, v0.w)),
                    fmaxf(fmaxf(v1.x, v1.y), fmaxf(v1.z, v1.w)));
#pragma unroll
    for (int o = 16; o > 0; o >>= 1)
        m = fmaxf(m, __shfl_xor_sync(0xffffffffu, m, o));

    __shared__ float red[8];
    if ((tid & 31) == 0) red[tid >> 5] = m;
    __syncthreads();
    float mall = red[0];
#pragma unroll
    for (int w = 1; w < 8; ++w) mall = fmaxf(mall, red[w]);
    __syncthreads();

    v0.x = __expf(v0.x - mall); v0.y = __expf(v0.y - mall);
    v0.z = __expf(v0.z - mall); v0.w = __expf(v0.w - mall);
    v1.x = __expf(v1.x - mall); v1.y = __expf(v1.y - mall);
    v1.z = __expf(v1.z - mall); v1.w = __expf(v1.w - mall);

    float s = v0.x + v0.y + v0.z + v0.w + v1.x + v1.y + v1.z + v1.w;
#pragma unroll
    for (int o = 16; o > 0; o >>= 1)
        s += __shfl_xor_sync(0xffffffffu, s, o);
    if ((tid & 31) == 0) red[tid >> 5] = s;
    __syncthreads();
    float sall = red[0];
#pragma unroll
    for (int w = 1; w < 8; ++w) sall += red[w];

    const float inv = 1.0f / sall;
    v0.x *= inv; v0.y *= inv; v0.z *= inv; v0.w *= inv;
    v1.x *= inv; v1.y *= inv; v1.z *= inv; v1.w *= inv;

    p[tid * 2 + 0] = v0;
    p[tid * 2 + 1] = v1;
}

// ---------------------------------------------------------------------------
extern "C" void kernel_launch(void* const* d_in, const int* in_sizes, int n_in,
                              void* d_out, int out_size)
{
    const float* Q = (const float*)d_in[0];
    const float* V = (const float*)d_in[1];

    float* ctx  = (float*)d_out;                          // [B,Lq,D]
    float* attn = (float*)d_out + (size_t)B_ * LQ * DD;   // [B,Lq,Lv]

    cudaFuncSetAttribute(mma_tf32_gemm<3>,
                         cudaFuncAttributeMaxDynamicSharedMemorySize, GEMM_SMEM);
    cudaFuncSetAttribute(mma_tf32_gemm<2>,
                         cudaFuncAttributeMaxDynamicSharedMemorySize, GEMM_SMEM);

    float* VT = nullptr;
    cudaGetSymbolAddress((void**)&VT, g_VT);

    // 0) VT = transpose(V)
    {
        dim3 grid(LV / 32, DD / 32, B_);
        transpose_vt_kernel<<<grid, dim3(32, 8)>>>(V, VT);
    }
    // 1) S = Q * V^T  (full 3xTF32) -> attn region
    {
        dim3 grid(LV / 128, LQ / 128, B_);
        mma_tf32_gemm<3><<<grid, 256, GEMM_SMEM>>>(Q, V, attn, LQ, LV, DD);
    }
    // 2) softmax rows in place
    softmax_kernel<<<B_ * LQ, 256>>>(attn);
    // 3) context = P * VT^T  (2-pass: P is softmax output in [0,1])
    {
        dim3 grid(DD / 128, LQ / 128, B_);
        mma_tf32_gemm<2><<<grid, 256, GEMM_SMEM>>>(attn, VT, ctx, LQ, DD, LV);
    }
}

// round 6
// speedup vs baseline: 2.3076x; 1.3631x over previous
#include <cuda_runtime.h>
#include <cuda_bf16.h>
#include <cstdint>

// Shape fixed by reference:
//   query [B=16, Lq=2048, D=512] f32, value [B=16, Lv=2048, D=512] f32
//   out = context [B,Lq,D] f32  ||  attn [B,Lq,Lv] f32
static constexpr int B_ = 16, LQ = 2048, LV = 2048, DD = 512;

// Scratch: V transposed per batch -> VT[b][d][v]
__device__ float g_VT[(size_t)B_ * DD * LV];

// ---------------------------------------------------------------------------
// cp.async helpers
// ---------------------------------------------------------------------------
__device__ __forceinline__ void cp16(uint32_t dst, const void* src) {
    asm volatile("cp.async.cg.shared.global [%0], [%1], 16;" :: "r"(dst), "l"(src));
}
#define CP_COMMIT() asm volatile("cp.async.commit_group;" ::: "memory")
template <int N>
__device__ __forceinline__ void cp_wait() {
    asm volatile("cp.async.wait_group %0;" :: "n"(N) : "memory");
}

// 2-term bf16 split of a k-adjacent fp32 pair (x = k, y = k+1):
//   hp = bf16x2(hi(x), hi(y)),  lp = bf16x2(x-hi(x), y-hi(y))
__device__ __forceinline__ void bf16_split2(float x, float y,
                                            uint32_t& hp, uint32_t& lp) {
    asm("cvt.rn.bf16x2.f32 %0, %1, %2;" : "=r"(hp) : "f"(y), "f"(x));
    float hx = __uint_as_float(hp << 16);
    float hy = __uint_as_float(hp & 0xFFFF0000u);
    asm("cvt.rn.bf16x2.f32 %0, %1, %2;" : "=r"(lp) : "f"(y - hy), "f"(x - hx));
}

__device__ __forceinline__ void mma16(float* d, const uint32_t* a, const uint32_t* b) {
    asm volatile(
        "mma.sync.aligned.m16n8k16.row.col.f32.bf16.bf16.f32 "
        "{%0,%1,%2,%3}, {%4,%5,%6,%7}, {%8,%9}, {%0,%1,%2,%3};"
        : "+f"(d[0]), "+f"(d[1]), "+f"(d[2]), "+f"(d[3])
        : "r"(a[0]), "r"(a[1]), "r"(a[2]), "r"(a[3]), "r"(b[0]), "r"(b[1]));
}

// ---------------------------------------------------------------------------
// Emulated-fp32 GEMM via 2-term bf16 split (3 products: hh + hl + lh):
//   C[M,N] = A[M,K] * B[N,K]^T   (both row-major, K contiguous)
// CTA tile 128x128, BK=32, 256 threads (8 warps, 2x4 of 64x32 warp tiles),
// 3-stage cp.async pipeline, one __syncthreads per stage, 2 CTAs/SM.
// ---------------------------------------------------------------------------
static constexpr int LDS_ROW = 36;                       // floats per smem row
static constexpr int TILE_F  = 128 * LDS_ROW;            // floats per tile
static constexpr int STAGES  = 3;
static constexpr int GEMM_SMEM = STAGES * 2 * TILE_F * 4;  // 110592 bytes

__global__ __launch_bounds__(256, 2)
void mma_bf16x2_gemm(const float* __restrict__ A, const float* __restrict__ Bm,
                     float* __restrict__ C, int M, int N, int K)
{
    extern __shared__ float sm[];
    const int tid  = threadIdx.x;
    const int wid  = tid >> 5, lane = tid & 31;
    const int gid  = lane >> 2, tig = lane & 3;
    const int wm   = wid & 1;        // 0..1  (64-row slabs)
    const int wn   = wid >> 1;       // 0..3  (32-col slabs)

    const size_t bz = blockIdx.z;
    A  += bz * (size_t)M * K;
    Bm += bz * (size_t)N * K;
    C  += bz * (size_t)M * N;
    const int row0 = blockIdx.y * 128;
    const int col0 = blockIdx.x * 128;

    const int lr = tid >> 3;          // 0..31
    const int lc = (tid & 7) * 4;     // 0,4,...,28
    const uint32_t smem_base = (uint32_t)__cvta_generic_to_shared(sm);

    auto load_stage = [&](int st, int k0) {
        const uint32_t a_off = smem_base + (uint32_t)(st * 2 * TILE_F) * 4u;
        const uint32_t b_off = smem_base + (uint32_t)((st * 2 + 1) * TILE_F) * 4u;
#pragma unroll
        for (int r = 0; r < 128; r += 32) {
            cp16(a_off + (uint32_t)((lr + r) * LDS_ROW + lc) * 4u,
                 &A[(size_t)(row0 + lr + r) * K + k0 + lc]);
            cp16(b_off + (uint32_t)((lr + r) * LDS_ROW + lc) * 4u,
                 &Bm[(size_t)(col0 + lr + r) * K + k0 + lc]);
        }
    };

    float acc[4][4][4];
#pragma unroll
    for (int mt = 0; mt < 4; ++mt)
#pragma unroll
        for (int nt = 0; nt < 4; ++nt)
#pragma unroll
            for (int i = 0; i < 4; ++i) acc[mt][nt][i] = 0.f;

    const int nsl = K / 32;
    load_stage(0, 0);  CP_COMMIT();
    load_stage(1, 32); CP_COMMIT();

    for (int s = 0; s < nsl; ++s) {
        cp_wait<1>();          // stage s resident
        __syncthreads();       // fences reuse of buffer (s+2)%3

        if (s + 2 < nsl) {
            load_stage((s + 2) % STAGES, (s + 2) * 32);
            CP_COMMIT();
        } else {
            CP_COMMIT();       // keep group count aligned for cp_wait<1>
        }

        const float* Asm = sm + (s % STAGES) * 2 * TILE_F;
        const float* Bsm = sm + ((s % STAGES) * 2 + 1) * TILE_F;

#pragma unroll
        for (int ks = 0; ks < 2; ++ks) {          // two k16 steps per BK=32
            const int kc = ks * 16 + 2 * tig;     // fp32 col of low element

            // B fragments: b0 = k (kc,kc+1), b1 = k (kc+8,kc+9), col gid
            uint32_t bhi[4][2], blo[4][2];
#pragma unroll
            for (int nt = 0; nt < 4; ++nt) {
                const float* bp = Bsm + (wn * 32 + nt * 8 + gid) * LDS_ROW + kc;
                float2 y0 = *(const float2*)bp;
                float2 y1 = *(const float2*)(bp + 8);
                bf16_split2(y0.x, y0.y, bhi[nt][0], blo[nt][0]);
                bf16_split2(y1.x, y1.y, bhi[nt][1], blo[nt][1]);
            }

#pragma unroll
            for (int mt = 0; mt < 4; ++mt) {
                const float* ap = Asm + (wm * 64 + mt * 16 + gid) * LDS_ROW + kc;
                float2 x0 = *(const float2*)ap;                     // row gid,   k kc
                float2 x1 = *(const float2*)(ap + 8 * LDS_ROW);     // row gid+8, k kc
                float2 x2 = *(const float2*)(ap + 8);               // row gid,   k kc+8
                float2 x3 = *(const float2*)(ap + 8 * LDS_ROW + 8); // row gid+8, k kc+8
                uint32_t ahi[4], alo[4];
                bf16_split2(x0.x, x0.y, ahi[0], alo[0]);
                bf16_split2(x1.x, x1.y, ahi[1], alo[1]);
                bf16_split2(x2.x, x2.y, ahi[2], alo[2]);
                bf16_split2(x3.x, x3.y, ahi[3], alo[3]);
                // pass-major order: accumulator reuse distance = 4
#pragma unroll
                for (int nt = 0; nt < 4; ++nt) mma16(acc[mt][nt], ahi, bhi[nt]);
#pragma unroll
                for (int nt = 0; nt < 4; ++nt) mma16(acc[mt][nt], ahi, blo[nt]);
#pragma unroll
                for (int nt = 0; nt < 4; ++nt) mma16(acc[mt][nt], alo, bhi[nt]);
            }
        }
    }

    // epilogue: c0,c1 at (row, 2*tig), c2,c3 at (row+8, 2*tig)
    __syncthreads();
#pragma unroll
    for (int mt = 0; mt < 4; ++mt) {
        const int rb = row0 + wm * 64 + mt * 16 + gid;
#pragma unroll
        for (int nt = 0; nt < 4; ++nt) {
            const int cb = col0 + wn * 32 + nt * 8 + 2 * tig;
            *(float2*)&C[(size_t)rb * N + cb] =
                make_float2(acc[mt][nt][0], acc[mt][nt][1]);
            *(float2*)&C[(size_t)(rb + 8) * N + cb] =
                make_float2(acc[mt][nt][2], acc[mt][nt][3]);
        }
    }
}

// ---------------------------------------------------------------------------
// V transpose: VT[b][d][v] = V[b][v][d]
// ---------------------------------------------------------------------------
__global__ __launch_bounds__(256)
void transpose_vt_kernel(const float* __restrict__ V, float* __restrict__ VT)
{
    __shared__ float t[32][33];
    const int b = blockIdx.z;
    const float* Vb = V + (size_t)b * LV * DD;
    float* VTb = VT + (size_t)b * DD * LV;
    const int v0 = blockIdx.x * 32, d0 = blockIdx.y * 32;
    const int tx = threadIdx.x, ty = threadIdx.y;  // 32 x 8
#pragma unroll
    for (int i = 0; i < 32; i += 8)
        t[ty + i][tx] = Vb[(size_t)(v0 + ty + i) * DD + d0 + tx];
    __syncthreads();
#pragma unroll
    for (int i = 0; i < 32; i += 8)
        VTb[(size_t)(d0 + ty + i) * LV + v0 + tx] = t[tx][ty + i];
}

// ---------------------------------------------------------------------------
// In-place row softmax over Lv=2048
// ---------------------------------------------------------------------------
__global__ __launch_bounds__(256)
void softmax_kernel(float* __restrict__ attn)
{
    const size_t row = blockIdx.x;
    float4* p = (float4*)(attn + row * (size_t)LV);
    const int tid = threadIdx.x;

    float4 v0 = p[tid * 2 + 0];
    float4 v1 = p[tid * 2 + 1];

    float m = fmaxf(fmaxf(fmaxf(v0.x, v0.y), fmaxf(v0.z, v0.w)),
                    fmaxf(fmaxf(v1.x, v1.y), fmaxf(v1.z, v1.w)));
#pragma unroll
    for (int o = 16; o > 0; o >>= 1)
        m = fmaxf(m, __shfl_xor_sync(0xffffffffu, m, o));

    __shared__ float red[8];
    if ((tid & 31) == 0) red[tid >> 5] = m;
    __syncthreads();
    float mall = red[0];
#pragma unroll
    for (int w = 1; w < 8; ++w) mall = fmaxf(mall, red[w]);
    __syncthreads();

    v0.x = __expf(v0.x - mall); v0.y = __expf(v0.y - mall);
    v0.z = __expf(v0.z - mall); v0.w = __expf(v0.w - mall);
    v1.x = __expf(v1.x - mall); v1.y = __expf(v1.y - mall);
    v1.z = __expf(v1.z - mall); v1.w = __expf(v1.w - mall);

    float s = v0.x + v0.y + v0.z + v0.w + v1.x + v1.y + v1.z + v1.w;
#pragma unroll
    for (int o = 16; o > 0; o >>= 1)
        s += __shfl_xor_sync(0xffffffffu, s, o);
    if ((tid & 31) == 0) red[tid >> 5] = s;
    __syncthreads();
    float sall = red[0];
#pragma unroll
    for (int w = 1; w < 8; ++w) sall += red[w];

    const float inv = 1.0f / sall;
    v0.x *= inv; v0.y *= inv; v0.z *= inv; v0.w *= inv;
    v1.x *= inv; v1.y *= inv; v1.z *= inv; v1.w *= inv;

    p[tid * 2 + 0] = v0;
    p[tid * 2 + 1] = v1;
}

// ---------------------------------------------------------------------------
extern "C" void kernel_launch(void* const* d_in, const int* in_sizes, int n_in,
                              void* d_out, int out_size)
{
    const float* Q = (const float*)d_in[0];
    const float* V = (const float*)d_in[1];

    float* ctx  = (float*)d_out;                          // [B,Lq,D]
    float* attn = (float*)d_out + (size_t)B_ * LQ * DD;   // [B,Lq,Lv]

    cudaFuncSetAttribute(mma_bf16x2_gemm,
                         cudaFuncAttributeMaxDynamicSharedMemorySize, GEMM_SMEM);

    float* VT = nullptr;
    cudaGetSymbolAddress((void**)&VT, g_VT);

    // 0) VT = transpose(V)
    {
        dim3 grid(LV / 32, DD / 32, B_);
        transpose_vt_kernel<<<grid, dim3(32, 8)>>>(V, VT);
    }
    // 1) S = Q * V^T  -> attn region
    {
        dim3 grid(LV / 128, LQ / 128, B_);
        mma_bf16x2_gemm<<<grid, 256, GEMM_SMEM>>>(Q, V, attn, LQ, LV, DD);
    }
    // 2) softmax rows in place
    softmax_kernel<<<B_ * LQ, 256>>>(attn);
    // 3) context = P * VT^T
    {
        dim3 grid(DD / 128, LQ / 128, B_);
        mma_bf16x2_gemm<<<grid, 256, GEMM_SMEM>>>(attn, VT, ctx, LQ, DD, LV);
    }
}

// round 7
// speedup vs baseline: 2.8338x; 1.2280x over previous
#include <cuda_runtime.h>
#include <cuda_bf16.h>
#include <cstdint>

// Shape fixed by reference:
//   query [B=16, Lq=2048, D=512] f32, value [B=16, Lv=2048, D=512] f32
//   out = context [B,Lq,D] f32  ||  attn [B,Lq,Lv] f32
static constexpr int B_ = 16, LQ = 2048, LV = 2048, DD = 512;

static constexpr size_t NQ = (size_t)B_ * LQ * DD;   // 16.7M
static constexpr size_t NV = (size_t)B_ * LV * DD;   // 16.7M
static constexpr size_t NP = (size_t)B_ * LQ * LV;   // 67.1M

// bf16 hi/lo scratch (global)
__device__ __nv_bfloat16 g_Qhi[NQ], g_Qlo[NQ];
__device__ __nv_bfloat16 g_Vhi[NV], g_Vlo[NV];
__device__ __nv_bfloat16 g_VThi[NV], g_VTlo[NV];     // [b][d][v]
__device__ __nv_bfloat16 g_Phi[NP], g_Plo[NP];

// ---------------------------------------------------------------------------
// helpers
// ---------------------------------------------------------------------------
__device__ __forceinline__ void cp16(uint32_t dst, const void* src) {
    asm volatile("cp.async.cg.shared.global [%0], [%1], 16;" :: "r"(dst), "l"(src));
}
#define CP_COMMIT() asm volatile("cp.async.commit_group;" ::: "memory")
template <int N>
__device__ __forceinline__ void cp_wait() {
    asm volatile("cp.async.wait_group %0;" :: "n"(N) : "memory");
}

// split pair (x,y) -> hi bf16x2 (low half = x), lo bf16x2
__device__ __forceinline__ void bf16_split2(float x, float y,
                                            uint32_t& hp, uint32_t& lp) {
    asm("cvt.rn.bf16x2.f32 %0, %1, %2;" : "=r"(hp) : "f"(y), "f"(x));
    float hx = __uint_as_float(hp << 16);
    float hy = __uint_as_float(hp & 0xFFFF0000u);
    asm("cvt.rn.bf16x2.f32 %0, %1, %2;" : "=r"(lp) : "f"(y - hy), "f"(x - hx));
}

__device__ __forceinline__ void mma16(float* d, const uint32_t* a, const uint32_t* b) {
    asm volatile(
        "mma.sync.aligned.m16n8k16.row.col.f32.bf16.bf16.f32 "
        "{%0,%1,%2,%3}, {%4,%5,%6,%7}, {%8,%9}, {%0,%1,%2,%3};"
        : "+f"(d[0]), "+f"(d[1]), "+f"(d[2]), "+f"(d[3])
        : "r"(a[0]), "r"(a[1]), "r"(a[2]), "r"(a[3]), "r"(b[0]), "r"(b[1]));
}

__device__ __forceinline__ void ldm4(uint32_t* r, uint32_t addr) {
    asm volatile("ldmatrix.sync.aligned.m8n8.x4.shared.b16 {%0,%1,%2,%3}, [%4];"
                 : "=r"(r[0]), "=r"(r[1]), "=r"(r[2]), "=r"(r[3]) : "r"(addr));
}

// ---------------------------------------------------------------------------
// bf16 GEMM, C[M,N] += over 3 products (hh + hl + lh):
//   A = (Ahi,Alo)[M,K], B = (Bhi,Blo)[N,K], row-major bf16, K contiguous.
// CTA tile 128x128, BK=32, 8 warps (2x4 of 64x32), 3-stage cp.async,
// XOR-swizzled smem (64B rows, 16B chunk c ^= (r>>1)&3), ldmatrix feeds.
// ---------------------------------------------------------------------------
static constexpr int ROWB    = 64;             // bytes per smem row (32 bf16)
static constexpr int TILE_B  = 128 * ROWB;     // 8 KB
static constexpr int STAGE_B = 4 * TILE_B;     // Ahi,Alo,Bhi,Blo = 32 KB
static constexpr int STAGES  = 3;
static constexpr int GEMM_SMEM = STAGES * STAGE_B;  // 96 KB

__global__ __launch_bounds__(256, 2)
void mma_bf16_gemm(const __nv_bfloat16* __restrict__ Ahi,
                   const __nv_bfloat16* __restrict__ Alo,
                   const __nv_bfloat16* __restrict__ Bhi,
                   const __nv_bfloat16* __restrict__ Blo,
                   float* __restrict__ C, int M, int N, int K)
{
    extern __shared__ char smc[];
    const uint32_t base = (uint32_t)__cvta_generic_to_shared(smc);

    const int tid = threadIdx.x;
    const int wid = tid >> 5, lane = tid & 31;
    const int gid = lane >> 2, tig = lane & 3;
    const int wm  = wid & 1;       // 64-row slab
    const int wn  = wid >> 1;      // 32-col slab

    const size_t bz = blockIdx.z;
    Ahi += bz * (size_t)M * K;  Alo += bz * (size_t)M * K;
    Bhi += bz * (size_t)N * K;  Blo += bz * (size_t)N * K;
    C   += bz * (size_t)M * N;
    const int row0 = blockIdx.y * 128;
    const int col0 = blockIdx.x * 128;

    // ---- loader: 512 chunks of 16B per tile; thread does chunks tid, tid+256
    const int i0 = tid, i1 = tid + 256;
    const int r0 = i0 >> 2, c0 = i0 & 3;
    const int r1 = i1 >> 2, c1 = i1 & 3;
    const uint32_t s0 = (uint32_t)(r0 * ROWB + ((c0 ^ ((r0 >> 1) & 3)) << 4));
    const uint32_t s1 = (uint32_t)(r1 * ROWB + ((c1 ^ ((r1 >> 1) & 3)) << 4));

    auto load_stage = [&](int st, int k0) {
        const uint32_t sb = base + (uint32_t)(st * STAGE_B);
        cp16(sb + s0,              &Ahi[(size_t)(row0 + r0) * K + k0 + c0 * 8]);
        cp16(sb + s1,              &Ahi[(size_t)(row0 + r1) * K + k0 + c1 * 8]);
        cp16(sb + TILE_B + s0,     &Alo[(size_t)(row0 + r0) * K + k0 + c0 * 8]);
        cp16(sb + TILE_B + s1,     &Alo[(size_t)(row0 + r1) * K + k0 + c1 * 8]);
        cp16(sb + 2 * TILE_B + s0, &Bhi[(size_t)(col0 + r0) * K + k0 + c0 * 8]);
        cp16(sb + 2 * TILE_B + s1, &Bhi[(size_t)(col0 + r1) * K + k0 + c1 * 8]);
        cp16(sb + 3 * TILE_B + s0, &Blo[(size_t)(col0 + r0) * K + k0 + c0 * 8]);
        cp16(sb + 3 * TILE_B + s1, &Blo[(size_t)(col0 + r1) * K + k0 + c1 * 8]);
    };

    // ---- ldmatrix lane addressing
    // A x4: matrices (rows+0,ch0)(rows+8,ch0)(rows+0,ch1)(rows+8,ch1) -> a0..a3
    const int a_row16 = ((lane >> 3) & 1) * 8 + (lane & 7);
    const int a_cpar  = (lane >> 4) & 1;
    uint32_t aoff[4]; int aswz[4];
#pragma unroll
    for (int mt = 0; mt < 4; ++mt) {
        const int r = wm * 64 + mt * 16 + a_row16;
        aoff[mt] = (uint32_t)(r * ROWB);
        aswz[mt] = (r >> 1) & 3;
    }
    // B x4 per pair p: matrices (n+0,ch0)(n+0,ch1)(n+8,ch0)(n+8,ch1)
    const int b_nadd = ((lane >> 4) & 1) * 8 + (lane & 7);
    const int b_cpar = (lane >> 3) & 1;
    uint32_t boff[2]; int bswz[2];
#pragma unroll
    for (int p = 0; p < 2; ++p) {
        const int n = wn * 32 + p * 16 + b_nadd;
        boff[p] = (uint32_t)(n * ROWB);
        bswz[p] = (n >> 1) & 3;
    }

    float acc[4][4][4];
#pragma unroll
    for (int mt = 0; mt < 4; ++mt)
#pragma unroll
        for (int nt = 0; nt < 4; ++nt)
#pragma unroll
            for (int i = 0; i < 4; ++i) acc[mt][nt][i] = 0.f;

    const int nsl = K / 32;
    load_stage(0, 0);  CP_COMMIT();
    load_stage(1, 32); CP_COMMIT();

    for (int s = 0; s < nsl; ++s) {
        cp_wait<1>();
        __syncthreads();

        if (s + 2 < nsl) {
            load_stage((s + 2) % STAGES, (s + 2) * 32);
            CP_COMMIT();
        } else {
            CP_COMMIT();   // keep group count aligned for cp_wait<1>
        }

        const uint32_t stg  = base + (uint32_t)((s % STAGES) * STAGE_B);
        const uint32_t Ahib = stg;
        const uint32_t Bhib = stg + 2 * TILE_B;

#pragma unroll
        for (int ks = 0; ks < 2; ++ks) {
            // ---- B fragments (4 nt, hi+lo) via 4 ldmatrix.x4
            uint32_t bhi[4][2], blo[4][2];
#pragma unroll
            for (int p = 0; p < 2; ++p) {
                uint32_t t[4];
                const uint32_t ad = Bhib + boff[p] +
                    (uint32_t)((((ks * 2 + b_cpar)) ^ bswz[p]) << 4);
                ldm4(t, ad);
                bhi[2 * p][0] = t[0]; bhi[2 * p][1] = t[1];
                bhi[2 * p + 1][0] = t[2]; bhi[2 * p + 1][1] = t[3];
                ldm4(t, ad + TILE_B);
                blo[2 * p][0] = t[0]; blo[2 * p][1] = t[1];
                blo[2 * p + 1][0] = t[2]; blo[2 * p + 1][1] = t[3];
            }

#pragma unroll
            for (int mt = 0; mt < 4; ++mt) {
                uint32_t ahi[4], alo[4];
                const uint32_t ad = Ahib + aoff[mt] +
                    (uint32_t)((((ks * 2 + a_cpar)) ^ aswz[mt]) << 4);
                ldm4(ahi, ad);
                ldm4(alo, ad + TILE_B);
#pragma unroll
                for (int nt = 0; nt < 4; ++nt) mma16(acc[mt][nt], ahi, bhi[nt]);
#pragma unroll
                for (int nt = 0; nt < 4; ++nt) mma16(acc[mt][nt], ahi, blo[nt]);
#pragma unroll
                for (int nt = 0; nt < 4; ++nt) mma16(acc[mt][nt], alo, bhi[nt]);
            }
        }
    }

    __syncthreads();
#pragma unroll
    for (int mt = 0; mt < 4; ++mt) {
        const int rb = row0 + wm * 64 + mt * 16 + gid;
#pragma unroll
        for (int nt = 0; nt < 4; ++nt) {
            const int cb = col0 + wn * 32 + nt * 8 + 2 * tig;
            *(float2*)&C[(size_t)rb * N + cb] =
                make_float2(acc[mt][nt][0], acc[mt][nt][1]);
            *(float2*)&C[(size_t)(rb + 8) * N + cb] =
                make_float2(acc[mt][nt][2], acc[mt][nt][3]);
        }
    }
}

// ---------------------------------------------------------------------------
// elementwise fp32 -> bf16 hi/lo split
// ---------------------------------------------------------------------------
__global__ __launch_bounds__(256)
void split_kernel(const float* __restrict__ X,
                  __nv_bfloat16* __restrict__ hi,
                  __nv_bfloat16* __restrict__ lo, int n4)
{
    const int i = blockIdx.x * 256 + threadIdx.x;
    if (i >= n4) return;
    float4 v = ((const float4*)X)[i];
    uint32_t h0, l0, h1, l1;
    bf16_split2(v.x, v.y, h0, l0);
    bf16_split2(v.z, v.w, h1, l1);
    ((uint2*)hi)[i] = make_uint2(h0, h1);
    ((uint2*)lo)[i] = make_uint2(l0, l1);
}

// ---------------------------------------------------------------------------
// V transpose + split: VThi/lo[b][d][v] = split(V[b][v][d])
// ---------------------------------------------------------------------------
__global__ __launch_bounds__(256)
void transpose_split_kernel(const float* __restrict__ V,
                            __nv_bfloat16* __restrict__ VThi,
                            __nv_bfloat16* __restrict__ VTlo)
{
    __shared__ float t[32][33];
    const int b = blockIdx.z;
    const float* Vb = V + (size_t)b * LV * DD;
    __nv_bfloat16* Hb = VThi + (size_t)b * DD * LV;
    __nv_bfloat16* Lb = VTlo + (size_t)b * DD * LV;
    const int v0 = blockIdx.x * 32, d0 = blockIdx.y * 32;
    const int tx = threadIdx.x, ty = threadIdx.y;  // 32 x 8
#pragma unroll
    for (int i = 0; i < 32; i += 8)
        t[ty + i][tx] = Vb[(size_t)(v0 + ty + i) * DD + d0 + tx];
    __syncthreads();
#pragma unroll
    for (int i = 0; i < 32; i += 8) {
        float x = t[tx][ty + i];
        __nv_bfloat16 h = __float2bfloat16(x);
        Hb[(size_t)(d0 + ty + i) * LV + v0 + tx] = h;
        Lb[(size_t)(d0 + ty + i) * LV + v0 + tx] =
            __float2bfloat16(x - __bfloat162float(h));
    }
}

// ---------------------------------------------------------------------------
// In-place row softmax over Lv=2048, also emits bf16 hi/lo of P
// ---------------------------------------------------------------------------
__global__ __launch_bounds__(256)
void softmax_kernel(float* __restrict__ attn,
                    __nv_bfloat16* __restrict__ Phi,
                    __nv_bfloat16* __restrict__ Plo)
{
    const size_t row = blockIdx.x;
    float4* p = (float4*)(attn + row * (size_t)LV);
    const int tid = threadIdx.x;

    float4 v0 = p[tid * 2 + 0];
    float4 v1 = p[tid * 2 + 1];

    float m = fmaxf(fmaxf(fmaxf(v0.x, v0.y), fmaxf(v0.z, v0.w)),
                    fmaxf(fmaxf(v1.x, v1.y), fmaxf(v1.z, v1.w)));
#pragma unroll
    for (int o = 16; o > 0; o >>= 1)
        m = fmaxf(m, __shfl_xor_sync(0xffffffffu, m, o));

    __shared__ float red[8];
    if ((tid & 31) == 0) red[tid >> 5] = m;
    __syncthreads();
    float mall = red[0];
#pragma unroll
    for (int w = 1; w < 8; ++w) mall = fmaxf(mall, red[w]);
    __syncthreads();

    v0.x = __expf(v0.x - mall); v0.y = __expf(v0.y - mall);
    v0.z = __expf(v0.z - mall); v0.w = __expf(v0.w - mall);
    v1.x = __expf(v1.x - mall); v1.y = __expf(v1.y - mall);
    v1.z = __expf(v1.z - mall); v1.w = __expf(v1.w - mall);

    float s = v0.x + v0.y + v0.z + v0.w + v1.x + v1.y + v1.z + v1.w;
#pragma unroll
    for (int o = 16; o > 0; o >>= 1)
        s += __shfl_xor_sync(0xffffffffu, s, o);
    if ((tid & 31) == 0) red[tid >> 5] = s;
    __syncthreads();
    float sall = red[0];
#pragma unroll
    for (int w = 1; w < 8; ++w) sall += red[w];

    const float inv = 1.0f / sall;
    v0.x *= inv; v0.y *= inv; v0.z *= inv; v0.w *= inv;
    v1.x *= inv; v1.y *= inv; v1.z *= inv; v1.w *= inv;

    p[tid * 2 + 0] = v0;
    p[tid * 2 + 1] = v1;

    uint32_t h0, l0, h1, l1, h2, l2, h3, l3;
    bf16_split2(v0.x, v0.y, h0, l0);
    bf16_split2(v0.z, v0.w, h1, l1);
    bf16_split2(v1.x, v1.y, h2, l2);
    bf16_split2(v1.z, v1.w, h3, l3);
    uint2* ph = (uint2*)(Phi + row * (size_t)LV);
    uint2* pl = (uint2*)(Plo + row * (size_t)LV);
    ph[tid * 2 + 0] = make_uint2(h0, h1);
    ph[tid * 2 + 1] = make_uint2(h2, h3);
    pl[tid * 2 + 0] = make_uint2(l0, l1);
    pl[tid * 2 + 1] = make_uint2(l2, l3);
}

// ---------------------------------------------------------------------------
extern "C" void kernel_launch(void* const* d_in, const int* in_sizes, int n_in,
                              void* d_out, int out_size)
{
    const float* Q = (const float*)d_in[0];
    const float* V = (const float*)d_in[1];

    float* ctx  = (float*)d_out;                          // [B,Lq,D]
    float* attn = (float*)d_out + (size_t)B_ * LQ * DD;   // [B,Lq,Lv]

    cudaFuncSetAttribute(mma_bf16_gemm,
                         cudaFuncAttributeMaxDynamicSharedMemorySize, GEMM_SMEM);

    __nv_bfloat16 *Qhi, *Qlo, *Vhi, *Vlo, *VThi, *VTlo, *Phi, *Plo;
    cudaGetSymbolAddress((void**)&Qhi, g_Qhi);
    cudaGetSymbolAddress((void**)&Qlo, g_Qlo);
    cudaGetSymbolAddress((void**)&Vhi, g_Vhi);
    cudaGetSymbolAddress((void**)&Vlo, g_Vlo);
    cudaGetSymbolAddress((void**)&VThi, g_VThi);
    cudaGetSymbolAddress((void**)&VTlo, g_VTlo);
    cudaGetSymbolAddress((void**)&Phi, g_Phi);
    cudaGetSymbolAddress((void**)&Plo, g_Plo);

    // 0) operand prep
    split_kernel<<<(int)(NQ / 4 / 256), 256>>>(Q, Qhi, Qlo, (int)(NQ / 4));
    split_kernel<<<(int)(NV / 4 / 256), 256>>>(V, Vhi, Vlo, (int)(NV / 4));
    {
        dim3 grid(LV / 32, DD / 32, B_);
        transpose_split_kernel<<<grid, dim3(32, 8)>>>(V, VThi, VTlo);
    }
    // 1) S = Q * V^T -> attn region
    {
        dim3 grid(LV / 128, LQ / 128, B_);
        mma_bf16_gemm<<<grid, 256, GEMM_SMEM>>>(Qhi, Qlo, Vhi, Vlo, attn, LQ, LV, DD);
    }
    // 2) softmax rows in place + emit P hi/lo
    softmax_kernel<<<B_ * LQ, 256>>>(attn, Phi, Plo);
    // 3) context = P * VT^T
    {
        dim3 grid(DD / 128, LQ / 128, B_);
        mma_bf16_gemm<<<grid, 256, GEMM_SMEM>>>(Phi, Plo, VThi, VTlo, ctx, LQ, DD, LV);
    }
}

// round 8
// speedup vs baseline: 3.3970x; 1.1988x over previous
#include <cuda_runtime.h>
#include <cuda_fp16.h>
#include <cstdint>

// Shape fixed by reference:
//   query [B=16, Lq=2048, D=512] f32, value [B=16, Lv=2048, D=512] f32
//   out = context [B,Lq,D] f32  ||  attn [B,Lq,Lv] f32
static constexpr int B_ = 16, LQ = 2048, LV = 2048, DD = 512;

static constexpr size_t NQ = (size_t)B_ * LQ * DD;
static constexpr size_t NV = (size_t)B_ * LV * DD;
static constexpr size_t NP = (size_t)B_ * LQ * LV;

// fp16 hi/lo scratch (global)
__device__ __half g_Qhi[NQ], g_Qlo[NQ];
__device__ __half g_Vhi[NV], g_Vlo[NV];
__device__ __half g_VThi[NV], g_VTlo[NV];     // [b][d][v]
__device__ __half g_Phi[NP];

// ---------------------------------------------------------------------------
// helpers
// ---------------------------------------------------------------------------
__device__ __forceinline__ void cp16(uint32_t dst, const void* src) {
    asm volatile("cp.async.cg.shared.global [%0], [%1], 16;" :: "r"(dst), "l"(src));
}
#define CP_COMMIT() asm volatile("cp.async.commit_group;" ::: "memory")
template <int N>
__device__ __forceinline__ void cp_wait() {
    asm volatile("cp.async.wait_group %0;" :: "n"(N) : "memory");
}

// split pair (x,y) -> hi half2 (low = x), lo half2
__device__ __forceinline__ void f16_split2(float x, float y,
                                           uint32_t& hp, uint32_t& lp) {
    __half2 h = __floats2half2_rn(x, y);
    hp = *reinterpret_cast<uint32_t*>(&h);
    float2 hf = __half22float2(h);
    __half2 l = __floats2half2_rn(x - hf.x, y - hf.y);
    lp = *reinterpret_cast<uint32_t*>(&l);
}

__device__ __forceinline__ void mma16(float* d, const uint32_t* a, const uint32_t* b) {
    asm volatile(
        "mma.sync.aligned.m16n8k16.row.col.f32.f16.f16.f32 "
        "{%0,%1,%2,%3}, {%4,%5,%6,%7}, {%8,%9}, {%0,%1,%2,%3};"
        : "+f"(d[0]), "+f"(d[1]), "+f"(d[2]), "+f"(d[3])
        : "r"(a[0]), "r"(a[1]), "r"(a[2]), "r"(a[3]), "r"(b[0]), "r"(b[1]));
}

__device__ __forceinline__ void ldm4(uint32_t* r, uint32_t addr) {
    asm volatile("ldmatrix.sync.aligned.m8n8.x4.shared.b16 {%0,%1,%2,%3}, [%4];"
                 : "=r"(r[0]), "=r"(r[1]), "=r"(r[2]), "=r"(r[3]) : "r"(addr));
}

// ---------------------------------------------------------------------------
// fp16 split GEMM:  C[M,N] = A[M,K]*B[N,K]^T
// PASSES=3: Ahi*Bhi + Ahi*Blo + Alo*Bhi  (full compensation)
// PASSES=2: Ahi*Bhi + Ahi*Blo            (A-lo dropped; A = softmax P)
// CTA 128x128, BK=32, 8 warps (2x4 of 64x32), 3-stage cp.async,
// XOR-swizzled smem (64B rows, chunk c ^= (r>>1)&3), ldmatrix feeds.
// ---------------------------------------------------------------------------
static constexpr int ROWB    = 64;             // bytes per smem row (32 halves)
static constexpr int TILE_B  = 128 * ROWB;     // 8 KB
static constexpr int STAGE_B = 4 * TILE_B;     // Ahi,Alo,Bhi,Blo slots = 32 KB
static constexpr int STAGES  = 3;
static constexpr int GEMM_SMEM = STAGES * STAGE_B;  // 96 KB

template <int PASSES>
__global__ __launch_bounds__(256, 2)
void mma_f16_gemm(const __half* __restrict__ Ahi,
                  const __half* __restrict__ Alo,
                  const __half* __restrict__ Bhi,
                  const __half* __restrict__ Blo,
                  float* __restrict__ C, int M, int N, int K)
{
    extern __shared__ char smc[];
    const uint32_t base = (uint32_t)__cvta_generic_to_shared(smc);

    const int tid = threadIdx.x;
    const int wid = tid >> 5, lane = tid & 31;
    const int gid = lane >> 2, tig = lane & 3;
    const int wm  = wid & 1;
    const int wn  = wid >> 1;

    const size_t bz = blockIdx.z;
    Ahi += bz * (size_t)M * K;  Alo += bz * (size_t)M * K;
    Bhi += bz * (size_t)N * K;  Blo += bz * (size_t)N * K;
    C   += bz * (size_t)M * N;
    const int row0 = blockIdx.y * 128;
    const int col0 = blockIdx.x * 128;

    // loader: 512 chunks of 16B per tile; thread does chunks tid, tid+256
    const int i0 = tid, i1 = tid + 256;
    const int r0 = i0 >> 2, c0 = i0 & 3;
    const int r1 = i1 >> 2, c1 = i1 & 3;
    const uint32_t s0 = (uint32_t)(r0 * ROWB + ((c0 ^ ((r0 >> 1) & 3)) << 4));
    const uint32_t s1 = (uint32_t)(r1 * ROWB + ((c1 ^ ((r1 >> 1) & 3)) << 4));

    auto load_stage = [&](int st, int k0) {
        const uint32_t sb = base + (uint32_t)(st * STAGE_B);
        cp16(sb + s0,              &Ahi[(size_t)(row0 + r0) * K + k0 + c0 * 8]);
        cp16(sb + s1,              &Ahi[(size_t)(row0 + r1) * K + k0 + c1 * 8]);
        if (PASSES == 3) {
            cp16(sb + TILE_B + s0, &Alo[(size_t)(row0 + r0) * K + k0 + c0 * 8]);
            cp16(sb + TILE_B + s1, &Alo[(size_t)(row0 + r1) * K + k0 + c1 * 8]);
        }
        cp16(sb + 2 * TILE_B + s0, &Bhi[(size_t)(col0 + r0) * K + k0 + c0 * 8]);
        cp16(sb + 2 * TILE_B + s1, &Bhi[(size_t)(col0 + r1) * K + k0 + c1 * 8]);
        cp16(sb + 3 * TILE_B + s0, &Blo[(size_t)(col0 + r0) * K + k0 + c0 * 8]);
        cp16(sb + 3 * TILE_B + s1, &Blo[(size_t)(col0 + r1) * K + k0 + c1 * 8]);
    };

    // ldmatrix lane addressing
    const int a_row16 = ((lane >> 3) & 1) * 8 + (lane & 7);
    const int a_cpar  = (lane >> 4) & 1;
    uint32_t aoff[4]; int aswz[4];
#pragma unroll
    for (int mt = 0; mt < 4; ++mt) {
        const int r = wm * 64 + mt * 16 + a_row16;
        aoff[mt] = (uint32_t)(r * ROWB);
        aswz[mt] = (r >> 1) & 3;
    }
    const int b_nadd = ((lane >> 4) & 1) * 8 + (lane & 7);
    const int b_cpar = (lane >> 3) & 1;
    uint32_t boff[2]; int bswz[2];
#pragma unroll
    for (int p = 0; p < 2; ++p) {
        const int n = wn * 32 + p * 16 + b_nadd;
        boff[p] = (uint32_t)(n * ROWB);
        bswz[p] = (n >> 1) & 3;
    }

    float acc[4][4][4];
#pragma unroll
    for (int mt = 0; mt < 4; ++mt)
#pragma unroll
        for (int nt = 0; nt < 4; ++nt)
#pragma unroll
            for (int i = 0; i < 4; ++i) acc[mt][nt][i] = 0.f;

    const int nsl = K / 32;
    load_stage(0, 0);  CP_COMMIT();
    load_stage(1, 32); CP_COMMIT();

    for (int s = 0; s < nsl; ++s) {
        cp_wait<1>();
        __syncthreads();

        if (s + 2 < nsl) {
            load_stage((s + 2) % STAGES, (s + 2) * 32);
            CP_COMMIT();
        } else {
            CP_COMMIT();   // keep group count aligned for cp_wait<1>
        }

        const uint32_t stg  = base + (uint32_t)((s % STAGES) * STAGE_B);
        const uint32_t Ahib = stg;
        const uint32_t Bhib = stg + 2 * TILE_B;

#pragma unroll
        for (int ks = 0; ks < 2; ++ks) {
            uint32_t bhi[4][2], blo[4][2];
#pragma unroll
            for (int p = 0; p < 2; ++p) {
                uint32_t t[4];
                const uint32_t ad = Bhib + boff[p] +
                    (uint32_t)(((ks * 2 + b_cpar) ^ bswz[p]) << 4);
                ldm4(t, ad);
                bhi[2 * p][0] = t[0]; bhi[2 * p][1] = t[1];
                bhi[2 * p + 1][0] = t[2]; bhi[2 * p + 1][1] = t[3];
                ldm4(t, ad + TILE_B);
                blo[2 * p][0] = t[0]; blo[2 * p][1] = t[1];
                blo[2 * p + 1][0] = t[2]; blo[2 * p + 1][1] = t[3];
            }

#pragma unroll
            for (int mt = 0; mt < 4; ++mt) {
                uint32_t ahi[4], alo[4];
                const uint32_t ad = Ahib + aoff[mt] +
                    (uint32_t)(((ks * 2 + a_cpar) ^ aswz[mt]) << 4);
                ldm4(ahi, ad);
                if (PASSES == 3) ldm4(alo, ad + TILE_B);
#pragma unroll
                for (int nt = 0; nt < 4; ++nt) mma16(acc[mt][nt], ahi, bhi[nt]);
#pragma unroll
                for (int nt = 0; nt < 4; ++nt) mma16(acc[mt][nt], ahi, blo[nt]);
                if (PASSES == 3) {
#pragma unroll
                    for (int nt = 0; nt < 4; ++nt) mma16(acc[mt][nt], alo, bhi[nt]);
                }
            }
        }
    }

    __syncthreads();
#pragma unroll
    for (int mt = 0; mt < 4; ++mt) {
        const int rb = row0 + wm * 64 + mt * 16 + gid;
#pragma unroll
        for (int nt = 0; nt < 4; ++nt) {
            const int cb = col0 + wn * 32 + nt * 8 + 2 * tig;
            *(float2*)&C[(size_t)rb * N + cb] =
                make_float2(acc[mt][nt][0], acc[mt][nt][1]);
            *(float2*)&C[(size_t)(rb + 8) * N + cb] =
                make_float2(acc[mt][nt][2], acc[mt][nt][3]);
        }
    }
}

// ---------------------------------------------------------------------------
// Q split: fp32 -> fp16 hi/lo
// ---------------------------------------------------------------------------
__global__ __launch_bounds__(256)
void split_kernel(const float* __restrict__ X,
                  __half* __restrict__ hi, __half* __restrict__ lo, int n4)
{
    const int i = blockIdx.x * 256 + threadIdx.x;
    if (i >= n4) return;
    float4 v = ((const float4*)X)[i];
    uint32_t h0, l0, h1, l1;
    f16_split2(v.x, v.y, h0, l0);
    f16_split2(v.z, v.w, h1, l1);
    ((uint2*)hi)[i] = make_uint2(h0, h1);
    ((uint2*)lo)[i] = make_uint2(l0, l1);
}

// ---------------------------------------------------------------------------
// Fused V prep: Vhi/Vlo [b][v][d]  +  VThi/VTlo [b][d][v]  (read V once)
// ---------------------------------------------------------------------------
__global__ __launch_bounds__(256)
void v_prep_kernel(const float* __restrict__ V,
                   __half* __restrict__ Vhi, __half* __restrict__ Vlo,
                   __half* __restrict__ VThi, __half* __restrict__ VTlo)
{
    __shared__ float t[32][33];
    const int b = blockIdx.z;
    const float* Vb = V + (size_t)b * LV * DD;
    const size_t ro = (size_t)b * LV * DD;   // row-major base
    const size_t to = (size_t)b * DD * LV;   // transposed base
    const int v0 = blockIdx.x * 32, d0 = blockIdx.y * 32;
    const int tx = threadIdx.x, ty = threadIdx.y;  // 32 x 8
#pragma unroll
    for (int i = 0; i < 32; i += 8) {
        float x = Vb[(size_t)(v0 + ty + i) * DD + d0 + tx];
        t[ty + i][tx] = x;
        __half h = __float2half(x);
        Vhi[ro + (size_t)(v0 + ty + i) * DD + d0 + tx] = h;
        Vlo[ro + (size_t)(v0 + ty + i) * DD + d0 + tx] =
            __float2half(x - __half2float(h));
    }
    __syncthreads();
#pragma unroll
    for (int i = 0; i < 32; i += 8) {
        float x = t[tx][ty + i];
        __half h = __float2half(x);
        VThi[to + (size_t)(d0 + ty + i) * LV + v0 + tx] = h;
        VTlo[to + (size_t)(d0 + ty + i) * LV + v0 + tx] =
            __float2half(x - __half2float(h));
    }
}

// ---------------------------------------------------------------------------
// In-place row softmax over Lv=2048, emits fp16 hi of P (lo not needed)
// ---------------------------------------------------------------------------
__global__ __launch_bounds__(256)
void softmax_kernel(float* __restrict__ attn, __half* __restrict__ Phi)
{
    const size_t row = blockIdx.x;
    float4* p = (float4*)(attn + row * (size_t)LV);
    const int tid = threadIdx.x;

    float4 v0 = p[tid * 2 + 0];
    float4 v1 = p[tid * 2 + 1];

    float m = fmaxf(fmaxf(fmaxf(v0.x, v0.y), fmaxf(v0.z, v0.w)),
                    fmaxf(fmaxf(v1.x, v1.y), fmaxf(v1.z, v1.w)));
#pragma unroll
    for (int o = 16; o > 0; o >>= 1)
        m = fmaxf(m, __shfl_xor_sync(0xffffffffu, m, o));

    __shared__ float red[8];
    if ((tid & 31) == 0) red[tid >> 5] = m;
    __syncthreads();
    float mall = red[0];
#pragma unroll
    for (int w = 1; w < 8; ++w) mall = fmaxf(mall, red[w]);
    __syncthreads();

    v0.x = __expf(v0.x - mall); v0.y = __expf(v0.y - mall);
    v0.z = __expf(v0.z - mall); v0.w = __expf(v0.w - mall);
    v1.x = __expf(v1.x - mall); v1.y = __expf(v1.y - mall);
    v1.z = __expf(v1.z - mall); v1.w = __expf(v1.w - mall);

    float s = v0.x + v0.y + v0.z + v0.w + v1.x + v1.y + v1.z + v1.w;
#pragma unroll
    for (int o = 16; o > 0; o >>= 1)
        s += __shfl_xor_sync(0xffffffffu, s, o);
    if ((tid & 31) == 0) red[tid >> 5] = s;
    __syncthreads();
    float sall = red[0];
#pragma unroll
    for (int w = 1; w < 8; ++w) sall += red[w];

    const float inv = 1.0f / sall;
    v0.x *= inv; v0.y *= inv; v0.z *= inv; v0.w *= inv;
    v1.x *= inv; v1.y *= inv; v1.z *= inv; v1.w *= inv;

    p[tid * 2 + 0] = v0;
    p[tid * 2 + 1] = v1;

    __half2 h0 = __floats2half2_rn(v0.x, v0.y);
    __half2 h1 = __floats2half2_rn(v0.z, v0.w);
    __half2 h2 = __floats2half2_rn(v1.x, v1.y);
    __half2 h3 = __floats2half2_rn(v1.z, v1.w);
    uint4 pk = make_uint4(*reinterpret_cast<uint32_t*>(&h0),
                          *reinterpret_cast<uint32_t*>(&h1),
                          *reinterpret_cast<uint32_t*>(&h2),
                          *reinterpret_cast<uint32_t*>(&h3));
    ((uint4*)(Phi + row * (size_t)LV))[tid] = pk;
}

// ---------------------------------------------------------------------------
extern "C" void kernel_launch(void* const* d_in, const int* in_sizes, int n_in,
                              void* d_out, int out_size)
{
    const float* Q = (const float*)d_in[0];
    const float* V = (const float*)d_in[1];

    float* ctx  = (float*)d_out;                          // [B,Lq,D]
    float* attn = (float*)d_out + (size_t)B_ * LQ * DD;   // [B,Lq,Lv]

    cudaFuncSetAttribute(mma_f16_gemm<3>,
                         cudaFuncAttributeMaxDynamicSharedMemorySize, GEMM_SMEM);
    cudaFuncSetAttribute(mma_f16_gemm<2>,
                         cudaFuncAttributeMaxDynamicSharedMemorySize, GEMM_SMEM);

    __half *Qhi, *Qlo, *Vhi, *Vlo, *VThi, *VTlo, *Phi;
    cudaGetSymbolAddress((void**)&Qhi, g_Qhi);
    cudaGetSymbolAddress((void**)&Qlo, g_Qlo);
    cudaGetSymbolAddress((void**)&Vhi, g_Vhi);
    cudaGetSymbolAddress((void**)&Vlo, g_Vlo);
    cudaGetSymbolAddress((void**)&VThi, g_VThi);
    cudaGetSymbolAddress((void**)&VTlo, g_VTlo);
    cudaGetSymbolAddress((void**)&Phi, g_Phi);

    // 0) operand prep
    split_kernel<<<(int)(NQ / 4 / 256), 256>>>(Q, Qhi, Qlo, (int)(NQ / 4));
    {
        dim3 grid(LV / 32, DD / 32, B_);
        v_prep_kernel<<<grid, dim3(32, 8)>>>(V, Vhi, Vlo, VThi, VTlo);
    }
    // 1) S = Q * V^T -> attn region (3 products: full compensation)
    {
        dim3 grid(LV / 128, LQ / 128, B_);
        mma_f16_gemm<3><<<grid, 256, GEMM_SMEM>>>(Qhi, Qlo, Vhi, Vlo, attn, LQ, LV, DD);
    }
    // 2) softmax rows in place + emit P hi
    softmax_kernel<<<B_ * LQ, 256>>>(attn, Phi);
    // 3) context = P * VT^T (2 products; P-lo term dropped, validated ~1.4e-4)
    {
        dim3 grid(DD / 128, LQ / 128, B_);
        mma_f16_gemm<2><<<grid, 256, GEMM_SMEM>>>(Phi, Phi, VThi, VTlo, ctx, LQ, DD, LV);
    }
}

// round 9
// speedup vs baseline: 3.9688x; 1.1683x over previous
#include <cuda_runtime.h>
#include <cuda_fp16.h>
#include <cstdint>

// Shape fixed by reference:
//   query [B=16, Lq=2048, D=512] f32, value [B=16, Lv=2048, D=512] f32
//   out = context [B,Lq,D] f32  ||  attn [B,Lq,Lv] f32
static constexpr int B_ = 16, LQ = 2048, LV = 2048, DD = 512;

static constexpr size_t NQ = (size_t)B_ * LQ * DD;
static constexpr size_t NV = (size_t)B_ * LV * DD;
static constexpr size_t NP = (size_t)B_ * LQ * LV;

// fp16 hi/lo scratch (global)
__device__ __half g_Qhi[NQ], g_Qlo[NQ];
__device__ __half g_Vhi[NV], g_Vlo[NV];
__device__ __half g_VThi[NV];                 // [b][d][v]
__device__ __half g_Phi[NP];

// ---------------------------------------------------------------------------
// helpers
// ---------------------------------------------------------------------------
__device__ __forceinline__ void cp16(uint32_t dst, const void* src) {
    asm volatile("cp.async.cg.shared.global [%0], [%1], 16;" :: "r"(dst), "l"(src));
}
#define CP_COMMIT() asm volatile("cp.async.commit_group;" ::: "memory")
template <int N>
__device__ __forceinline__ void cp_wait() {
    asm volatile("cp.async.wait_group %0;" :: "n"(N) : "memory");
}

// split pair (x,y) -> hi half2 (low = x), lo half2
__device__ __forceinline__ void f16_split2(float x, float y,
                                           uint32_t& hp, uint32_t& lp) {
    __half2 h = __floats2half2_rn(x, y);
    hp = *reinterpret_cast<uint32_t*>(&h);
    float2 hf = __half22float2(h);
    __half2 l = __floats2half2_rn(x - hf.x, y - hf.y);
    lp = *reinterpret_cast<uint32_t*>(&l);
}

__device__ __forceinline__ void mma16(float* d, const uint32_t* a, const uint32_t* b) {
    asm volatile(
        "mma.sync.aligned.m16n8k16.row.col.f32.f16.f16.f32 "
        "{%0,%1,%2,%3}, {%4,%5,%6,%7}, {%8,%9}, {%0,%1,%2,%3};"
        : "+f"(d[0]), "+f"(d[1]), "+f"(d[2]), "+f"(d[3])
        : "r"(a[0]), "r"(a[1]), "r"(a[2]), "r"(a[3]), "r"(b[0]), "r"(b[1]));
}

__device__ __forceinline__ void ldm4(uint32_t* r, uint32_t addr) {
    asm volatile("ldmatrix.sync.aligned.m8n8.x4.shared.b16 {%0,%1,%2,%3}, [%4];"
                 : "=r"(r[0]), "=r"(r[1]), "=r"(r[2]), "=r"(r[3]) : "r"(addr));
}

// ---------------------------------------------------------------------------
// fp16 split GEMM:  C[M,N] = A[M,K]*B[N,K]^T
// PASSES=3: Ahi*Bhi + Ahi*Blo + Alo*Bhi  (full compensation)
// PASSES=1: Ahi*Bhi                       (P*Vhi; dropped terms ~2e-4 total)
// CTA 128x128, BK=32, 8 warps (2x4 of 64x32), 3-stage cp.async,
// XOR-swizzled smem (64B rows, chunk c ^= (r>>1)&3), ldmatrix feeds.
// ---------------------------------------------------------------------------
static constexpr int ROWB    = 64;             // bytes per smem row (32 halves)
static constexpr int TILE_B  = 128 * ROWB;     // 8 KB
static constexpr int STAGE_B = 4 * TILE_B;     // Ahi,Alo,Bhi,Blo slots = 32 KB
static constexpr int STAGES  = 3;
static constexpr int GEMM_SMEM = STAGES * STAGE_B;  // 96 KB

template <int PASSES>
__global__ __launch_bounds__(256, 2)
void mma_f16_gemm(const __half* __restrict__ Ahi,
                  const __half* __restrict__ Alo,
                  const __half* __restrict__ Bhi,
                  const __half* __restrict__ Blo,
                  float* __restrict__ C, int M, int N, int K)
{
    extern __shared__ char smc[];
    const uint32_t base = (uint32_t)__cvta_generic_to_shared(smc);

    const int tid = threadIdx.x;
    const int wid = tid >> 5, lane = tid & 31;
    const int gid = lane >> 2, tig = lane & 3;
    const int wm  = wid & 1;
    const int wn  = wid >> 1;

    const size_t bz = blockIdx.z;
    Ahi += bz * (size_t)M * K;  Alo += bz * (size_t)M * K;
    Bhi += bz * (size_t)N * K;  Blo += bz * (size_t)N * K;
    C   += bz * (size_t)M * N;
    const int row0 = blockIdx.y * 128;
    const int col0 = blockIdx.x * 128;

    // loader: 512 chunks of 16B per tile; thread does chunks tid, tid+256
    const int i0 = tid, i1 = tid + 256;
    const int r0 = i0 >> 2, c0 = i0 & 3;
    const int r1 = i1 >> 2, c1 = i1 & 3;
    const uint32_t s0 = (uint32_t)(r0 * ROWB + ((c0 ^ ((r0 >> 1) & 3)) << 4));
    const uint32_t s1 = (uint32_t)(r1 * ROWB + ((c1 ^ ((r1 >> 1) & 3)) << 4));

    auto load_stage = [&](int st, int k0) {
        const uint32_t sb = base + (uint32_t)(st * STAGE_B);
        cp16(sb + s0,              &Ahi[(size_t)(row0 + r0) * K + k0 + c0 * 8]);
        cp16(sb + s1,              &Ahi[(size_t)(row0 + r1) * K + k0 + c1 * 8]);
        if (PASSES == 3) {
            cp16(sb + TILE_B + s0, &Alo[(size_t)(row0 + r0) * K + k0 + c0 * 8]);
            cp16(sb + TILE_B + s1, &Alo[(size_t)(row0 + r1) * K + k0 + c1 * 8]);
        }
        cp16(sb + 2 * TILE_B + s0, &Bhi[(size_t)(col0 + r0) * K + k0 + c0 * 8]);
        cp16(sb + 2 * TILE_B + s1, &Bhi[(size_t)(col0 + r1) * K + k0 + c1 * 8]);
        if (PASSES == 3) {
            cp16(sb + 3 * TILE_B + s0, &Blo[(size_t)(col0 + r0) * K + k0 + c0 * 8]);
            cp16(sb + 3 * TILE_B + s1, &Blo[(size_t)(col0 + r1) * K + k0 + c1 * 8]);
        }
    };

    // ldmatrix lane addressing
    const int a_row16 = ((lane >> 3) & 1) * 8 + (lane & 7);
    const int a_cpar  = (lane >> 4) & 1;
    uint32_t aoff[4]; int aswz[4];
#pragma unroll
    for (int mt = 0; mt < 4; ++mt) {
        const int r = wm * 64 + mt * 16 + a_row16;
        aoff[mt] = (uint32_t)(r * ROWB);
        aswz[mt] = (r >> 1) & 3;
    }
    const int b_nadd = ((lane >> 4) & 1) * 8 + (lane & 7);
    const int b_cpar = (lane >> 3) & 1;
    uint32_t boff[2]; int bswz[2];
#pragma unroll
    for (int p = 0; p < 2; ++p) {
        const int n = wn * 32 + p * 16 + b_nadd;
        boff[p] = (uint32_t)(n * ROWB);
        bswz[p] = (n >> 1) & 3;
    }

    float acc[4][4][4];
#pragma unroll
    for (int mt = 0; mt < 4; ++mt)
#pragma unroll
        for (int nt = 0; nt < 4; ++nt)
#pragma unroll
            for (int i = 0; i < 4; ++i) acc[mt][nt][i] = 0.f;

    const int nsl = K / 32;
    load_stage(0, 0);  CP_COMMIT();
    load_stage(1, 32); CP_COMMIT();

    for (int s = 0; s < nsl; ++s) {
        cp_wait<1>();
        __syncthreads();

        if (s + 2 < nsl) {
            load_stage((s + 2) % STAGES, (s + 2) * 32);
            CP_COMMIT();
        } else {
            CP_COMMIT();   // keep group count aligned for cp_wait<1>
        }

        const uint32_t stg  = base + (uint32_t)((s % STAGES) * STAGE_B);
        const uint32_t Ahib = stg;
        const uint32_t Bhib = stg + 2 * TILE_B;

#pragma unroll
        for (int ks = 0; ks < 2; ++ks) {
            uint32_t bhi[4][2], blo[4][2];
#pragma unroll
            for (int p = 0; p < 2; ++p) {
                uint32_t t[4];
                const uint32_t ad = Bhib + boff[p] +
                    (uint32_t)(((ks * 2 + b_cpar) ^ bswz[p]) << 4);
                ldm4(t, ad);
                bhi[2 * p][0] = t[0]; bhi[2 * p][1] = t[1];
                bhi[2 * p + 1][0] = t[2]; bhi[2 * p + 1][1] = t[3];
                if (PASSES == 3) {
                    ldm4(t, ad + TILE_B);
                    blo[2 * p][0] = t[0]; blo[2 * p][1] = t[1];
                    blo[2 * p + 1][0] = t[2]; blo[2 * p + 1][1] = t[3];
                }
            }

#pragma unroll
            for (int mt = 0; mt < 4; ++mt) {
                uint32_t ahi[4], alo[4];
                const uint32_t ad = Ahib + aoff[mt] +
                    (uint32_t)(((ks * 2 + a_cpar) ^ aswz[mt]) << 4);
                ldm4(ahi, ad);
                if (PASSES == 3) ldm4(alo, ad + TILE_B);
#pragma unroll
                for (int nt = 0; nt < 4; ++nt) mma16(acc[mt][nt], ahi, bhi[nt]);
                if (PASSES == 3) {
#pragma unroll
                    for (int nt = 0; nt < 4; ++nt) mma16(acc[mt][nt], ahi, blo[nt]);
#pragma unroll
                    for (int nt = 0; nt < 4; ++nt) mma16(acc[mt][nt], alo, bhi[nt]);
                }
            }
        }
    }

    __syncthreads();
#pragma unroll
    for (int mt = 0; mt < 4; ++mt) {
        const int rb = row0 + wm * 64 + mt * 16 + gid;
#pragma unroll
        for (int nt = 0; nt < 4; ++nt) {
            const int cb = col0 + wn * 32 + nt * 8 + 2 * tig;
            *(float2*)&C[(size_t)rb * N + cb] =
                make_float2(acc[mt][nt][0], acc[mt][nt][1]);
            *(float2*)&C[(size_t)(rb + 8) * N + cb] =
                make_float2(acc[mt][nt][2], acc[mt][nt][3]);
        }
    }
}

// ---------------------------------------------------------------------------
// Q split: fp32 -> fp16 hi/lo
// ---------------------------------------------------------------------------
__global__ __launch_bounds__(256)
void split_kernel(const float* __restrict__ X,
                  __half* __restrict__ hi, __half* __restrict__ lo, int n4)
{
    const int i = blockIdx.x * 256 + threadIdx.x;
    if (i >= n4) return;
    float4 v = ((const float4*)X)[i];
    uint32_t h0, l0, h1, l1;
    f16_split2(v.x, v.y, h0, l0);
    f16_split2(v.z, v.w, h1, l1);
    ((uint2*)hi)[i] = make_uint2(h0, h1);
    ((uint2*)lo)[i] = make_uint2(l0, l1);
}

// ---------------------------------------------------------------------------
// Fused V prep: Vhi/Vlo [b][v][d]  +  VThi [b][d][v]  (read V once)
// ---------------------------------------------------------------------------
__global__ __launch_bounds__(256)
void v_prep_kernel(const float* __restrict__ V,
                   __half* __restrict__ Vhi, __half* __restrict__ Vlo,
                   __half* __restrict__ VThi)
{
    __shared__ float t[32][33];
    const int b = blockIdx.z;
    const float* Vb = V + (size_t)b * LV * DD;
    const size_t ro = (size_t)b * LV * DD;   // row-major base
    const size_t to = (size_t)b * DD * LV;   // transposed base
    const int v0 = blockIdx.x * 32, d0 = blockIdx.y * 32;
    const int tx = threadIdx.x, ty = threadIdx.y;  // 32 x 8
#pragma unroll
    for (int i = 0; i < 32; i += 8) {
        float x = Vb[(size_t)(v0 + ty + i) * DD + d0 + tx];
        t[ty + i][tx] = x;
        __half h = __float2half(x);
        Vhi[ro + (size_t)(v0 + ty + i) * DD + d0 + tx] = h;
        Vlo[ro + (size_t)(v0 + ty + i) * DD + d0 + tx] =
            __float2half(x - __half2float(h));
    }
    __syncthreads();
#pragma unroll
    for (int i = 0; i < 32; i += 8)
        VThi[to + (size_t)(d0 + ty + i) * LV + v0 + tx] =
            __float2half(t[tx][ty + i]);
}

// ---------------------------------------------------------------------------
// In-place row softmax over Lv=2048, emits fp16 hi of P
// ---------------------------------------------------------------------------
__global__ __launch_bounds__(256)
void softmax_kernel(float* __restrict__ attn, __half* __restrict__ Phi)
{
    const size_t row = blockIdx.x;
    float4* p = (float4*)(attn + row * (size_t)LV);
    const int tid = threadIdx.x;

    float4 v0 = p[tid * 2 + 0];
    float4 v1 = p[tid * 2 + 1];

    float m = fmaxf(fmaxf(fmaxf(v0.x, v0.y), fmaxf(v0.z, v0.w)),
                    fmaxf(fmaxf(v1.x, v1.y), fmaxf(v1.z, v1.w)));
#pragma unroll
    for (int o = 16; o > 0; o >>= 1)
        m = fmaxf(m, __shfl_xor_sync(0xffffffffu, m, o));

    __shared__ float red[8];
    if ((tid & 31) == 0) red[tid >> 5] = m;
    __syncthreads();
    float mall = red[0];
#pragma unroll
    for (int w = 1; w < 8; ++w) mall = fmaxf(mall, red[w]);
    __syncthreads();

    v0.x = __expf(v0.x - mall); v0.y = __expf(v0.y - mall);
    v0.z = __expf(v0.z - mall); v0.w = __expf(v0.w - mall);
    v1.x = __expf(v1.x - mall); v1.y = __expf(v1.y - mall);
    v1.z = __expf(v1.z - mall); v1.w = __expf(v1.w - mall);

    float s = v0.x + v0.y + v0.z + v0.w + v1.x + v1.y + v1.z + v1.w;
#pragma unroll
    for (int o = 16; o > 0; o >>= 1)
        s += __shfl_xor_sync(0xffffffffu, s, o);
    if ((tid & 31) == 0) red[tid >> 5] = s;
    __syncthreads();
    float sall = red[0];
#pragma unroll
    for (int w = 1; w < 8; ++w) sall += red[w];

    const float inv = 1.0f / sall;
    v0.x *= inv; v0.y *= inv; v0.z *= inv; v0.w *= inv;
    v1.x *= inv; v1.y *= inv; v1.z *= inv; v1.w *= inv;

    p[tid * 2 + 0] = v0;
    p[tid * 2 + 1] = v1;

    __half2 h0 = __floats2half2_rn(v0.x, v0.y);
    __half2 h1 = __floats2half2_rn(v0.z, v0.w);
    __half2 h2 = __floats2half2_rn(v1.x, v1.y);
    __half2 h3 = __floats2half2_rn(v1.z, v1.w);
    uint4 pk = make_uint4(*reinterpret_cast<uint32_t*>(&h0),
                          *reinterpret_cast<uint32_t*>(&h1),
                          *reinterpret_cast<uint32_t*>(&h2),
                          *reinterpret_cast<uint32_t*>(&h3));
    ((uint4*)(Phi + row * (size_t)LV))[tid] = pk;
}

// ---------------------------------------------------------------------------
extern "C" void kernel_launch(void* const* d_in, const int* in_sizes, int n_in,
                              void* d_out, int out_size)
{
    const float* Q = (const float*)d_in[0];
    const float* V = (const float*)d_in[1];

    float* ctx  = (float*)d_out;                          // [B,Lq,D]
    float* attn = (float*)d_out + (size_t)B_ * LQ * DD;   // [B,Lq,Lv]

    cudaFuncSetAttribute(mma_f16_gemm<3>,
                         cudaFuncAttributeMaxDynamicSharedMemorySize, GEMM_SMEM);
    cudaFuncSetAttribute(mma_f16_gemm<1>,
                         cudaFuncAttributeMaxDynamicSharedMemorySize, GEMM_SMEM);

    __half *Qhi, *Qlo, *Vhi, *Vlo, *VThi, *Phi;
    cudaGetSymbolAddress((void**)&Qhi, g_Qhi);
    cudaGetSymbolAddress((void**)&Qlo, g_Qlo);
    cudaGetSymbolAddress((void**)&Vhi, g_Vhi);
    cudaGetSymbolAddress((void**)&Vlo, g_Vlo);
    cudaGetSymbolAddress((void**)&VThi, g_VThi);
    cudaGetSymbolAddress((void**)&Phi, g_Phi);

    // 0) operand prep
    split_kernel<<<(int)(NQ / 4 / 256), 256>>>(Q, Qhi, Qlo, (int)(NQ / 4));
    {
        dim3 grid(LV / 32, DD / 32, B_);
        v_prep_kernel<<<grid, dim3(32, 8)>>>(V, Vhi, Vlo, VThi);
    }
    // 1) S = Q * V^T -> attn region (3 products: full compensation)
    {
        dim3 grid(LV / 128, LQ / 128, B_);
        mma_f16_gemm<3><<<grid, 256, GEMM_SMEM>>>(Qhi, Qlo, Vhi, Vlo, attn, LQ, LV, DD);
    }
    // 2) softmax rows in place + emit P hi
    softmax_kernel<<<B_ * LQ, 256>>>(attn, Phi);
    // 3) context = Phi * VThi^T (1 product; dropped terms ~2e-4 combined)
    {
        dim3 grid(DD / 128, LQ / 128, B_);
        mma_f16_gemm<1><<<grid, 256, GEMM_SMEM>>>(Phi, Phi, VThi, VThi, ctx, LQ, DD, LV);
    }
}